// round 5
// baseline (speedup 1.0000x reference)
#include <cuda_runtime.h>
#include <math.h>

#define S_    2048
#define HID_  2048
#define H_    16
#define NOPE_ 128
#define ROPE_ 64
#define VDIM_ 128
#define QR_   1536
#define KVR_  512
#define IH_   16
#define ID_   128
#define TOPK_ 512
#define EPS_  1e-6f
#define CKVW_ (KVR_ + ROPE_)

// ---------------- scratch ----------------
__device__ float g_qr    [S_*QR_];
__device__ float g_q     [S_*H_*(NOPE_+ROPE_)];
__device__ float g_ckvpart[4*S_*CKVW_];
__device__ float g_ckvn  [S_*KVR_];
__device__ float g_kpe   [S_*ROPE_];
__device__ float g_kv    [S_*H_*(NOPE_+VDIM_)];
__device__ float g_iq    [S_*IH_*ID_];
__device__ float g_ikpre [S_*ID_];
__device__ float g_ik    [S_*ID_];
__device__ float g_iw    [S_*IH_];
__device__ float g_scores[S_*S_];
__device__ int   g_sel   [S_*TOPK_];
__device__ int   g_nsel  [S_];
__device__ float g_attn  [S_*H_*VDIM_];
__device__ float g_cosb  [S_*32];
__device__ float g_sinb  [S_*32];

// ---------------- helpers ----------------
__device__ __forceinline__ float blockReduceSum(float v, float* sh) {
    int lane = threadIdx.x & 31, w = threadIdx.x >> 5;
    #pragma unroll
    for (int o = 16; o; o >>= 1) v += __shfl_xor_sync(0xffffffffu, v, o);
    if (lane == 0) sh[w] = v;
    __syncthreads();
    int nw = (blockDim.x + 31) >> 5;
    float r = (threadIdx.x < nw) ? sh[threadIdx.x] : 0.f;
    if (w == 0) {
        #pragma unroll
        for (int o = 16; o; o >>= 1) r += __shfl_xor_sync(0xffffffffu, r, o);
        if (lane == 0) sh[0] = r;
    }
    __syncthreads();
    float out = sh[0];
    __syncthreads();
    return out;
}

// ---------------- cos/sin (bit-exact numpy float32 path) ----------------
__global__ void cossin_kernel() {
    int s = blockIdx.x, d = threadIdx.x;
    float e = (float)(2 * d) / 64.0f;
    float pf = (float)pow(10000.0, (double)e);
    float inv = __fdiv_rn(1.0f, pf);
    float f = __fmul_rn((float)s, inv);
    g_cosb[s * 32 + d] = (float)cos((double)f);
    g_sinb[s * 32 + d] = (float)sin((double)f);
}

// ============ double-buffered SGEMM 128x128: C = alpha * A[M,K] @ B[N,K]^T ============
__global__ __launch_bounds__(256) void sgemm_nt_db(
    const float* __restrict__ A, int lda,
    const float* __restrict__ B, int ldb,
    float* __restrict__ C, int ldc,
    int M, int N, int K, float alpha)
{
    __shared__ float As[2][8][128];
    __shared__ float Bs[2][8][128];
    int m0 = blockIdx.y * 128, n0 = blockIdx.x * 128;
    int t = threadIdx.x;
    int tx = t & 15, ty = t >> 4;
    int a_m = t >> 1, a_k = (t & 1) * 4;
    int gmA = m0 + a_m, gnB = n0 + a_m;
    float acc[8][8];
    #pragma unroll
    for (int i = 0; i < 8; i++)
        #pragma unroll
        for (int j = 0; j < 8; j++) acc[i][j] = 0.f;

    float4 va = make_float4(0.f,0.f,0.f,0.f), vb = va;
    if (gmA < M) va = *reinterpret_cast<const float4*>(&A[(size_t)gmA * lda + a_k]);
    if (gnB < N) vb = *reinterpret_cast<const float4*>(&B[(size_t)gnB * ldb + a_k]);
    As[0][a_k+0][a_m]=va.x; As[0][a_k+1][a_m]=va.y; As[0][a_k+2][a_m]=va.z; As[0][a_k+3][a_m]=va.w;
    Bs[0][a_k+0][a_m]=vb.x; Bs[0][a_k+1][a_m]=vb.y; Bs[0][a_k+2][a_m]=vb.z; Bs[0][a_k+3][a_m]=vb.w;
    __syncthreads();
    int buf = 0;
    for (int k0 = 0; k0 < K; k0 += 8) {
        bool nxt = (k0 + 8) < K;
        if (nxt) {
            va = make_float4(0.f,0.f,0.f,0.f); vb = va;
            if (gmA < M) va = *reinterpret_cast<const float4*>(&A[(size_t)gmA * lda + k0 + 8 + a_k]);
            if (gnB < N) vb = *reinterpret_cast<const float4*>(&B[(size_t)gnB * ldb + k0 + 8 + a_k]);
        }
        #pragma unroll
        for (int k = 0; k < 8; k++) {
            float4 a0 = *reinterpret_cast<const float4*>(&As[buf][k][ty * 8]);
            float4 a1 = *reinterpret_cast<const float4*>(&As[buf][k][ty * 8 + 4]);
            float4 b0 = *reinterpret_cast<const float4*>(&Bs[buf][k][tx * 8]);
            float4 b1 = *reinterpret_cast<const float4*>(&Bs[buf][k][tx * 8 + 4]);
            float ra[8] = {a0.x,a0.y,a0.z,a0.w,a1.x,a1.y,a1.z,a1.w};
            float rb[8] = {b0.x,b0.y,b0.z,b0.w,b1.x,b1.y,b1.z,b1.w};
            #pragma unroll
            for (int i = 0; i < 8; i++)
                #pragma unroll
                for (int j = 0; j < 8; j++) acc[i][j] += ra[i] * rb[j];
        }
        if (nxt) {
            int nb = buf ^ 1;
            As[nb][a_k+0][a_m]=va.x; As[nb][a_k+1][a_m]=va.y; As[nb][a_k+2][a_m]=va.z; As[nb][a_k+3][a_m]=va.w;
            Bs[nb][a_k+0][a_m]=vb.x; Bs[nb][a_k+1][a_m]=vb.y; Bs[nb][a_k+2][a_m]=vb.z; Bs[nb][a_k+3][a_m]=vb.w;
            __syncthreads();
            buf = nb;
        }
    }
    #pragma unroll
    for (int i = 0; i < 8; i++) {
        int gm = m0 + ty * 8 + i;
        if (gm >= M) continue;
        #pragma unroll
        for (int j = 0; j < 8; j++) {
            int gn = n0 + tx * 8 + j;
            if (gn < N) C[(size_t)gm * ldc + gn] = alpha * acc[i][j];
        }
    }
}

// ============ 64x64-tile SGEMM (for thin N) — per-output k-order identical ============
__global__ __launch_bounds__(256) void sgemm_nt_64(
    const float* __restrict__ A, int lda,
    const float* __restrict__ B, int ldb,
    float* __restrict__ C, int ldc,
    int M, int N, int K, float alpha)
{
    __shared__ float As[2][8][64];
    __shared__ float Bs[2][8][64];
    int m0 = blockIdx.y * 64, n0 = blockIdx.x * 64;
    int t = threadIdx.x;
    int tx = t & 15, ty = t >> 4;           // 16 x 16 threads, 4x4 microtile
    int lt = t & 127;
    int l_m = lt >> 1, l_k = (lt & 1) * 4;
    bool isA = t < 128;
    int grow = (isA ? m0 : n0) + l_m;
    int lim = isA ? M : N;
    const float* P = isA ? A : B;
    int ldp = isA ? lda : ldb;

    float acc[4][4];
    #pragma unroll
    for (int i = 0; i < 4; i++)
        #pragma unroll
        for (int j = 0; j < 4; j++) acc[i][j] = 0.f;

    float4 v = make_float4(0.f,0.f,0.f,0.f);
    if (grow < lim) v = *reinterpret_cast<const float4*>(&P[(size_t)grow * ldp + l_k]);
    if (isA) { As[0][l_k+0][l_m]=v.x; As[0][l_k+1][l_m]=v.y; As[0][l_k+2][l_m]=v.z; As[0][l_k+3][l_m]=v.w; }
    else     { Bs[0][l_k+0][l_m]=v.x; Bs[0][l_k+1][l_m]=v.y; Bs[0][l_k+2][l_m]=v.z; Bs[0][l_k+3][l_m]=v.w; }
    __syncthreads();
    int buf = 0;
    for (int k0 = 0; k0 < K; k0 += 8) {
        bool nxt = (k0 + 8) < K;
        if (nxt) {
            v = make_float4(0.f,0.f,0.f,0.f);
            if (grow < lim) v = *reinterpret_cast<const float4*>(&P[(size_t)grow * ldp + k0 + 8 + l_k]);
        }
        #pragma unroll
        for (int k = 0; k < 8; k++) {
            float4 a0 = *reinterpret_cast<const float4*>(&As[buf][k][ty * 4]);
            float4 b0 = *reinterpret_cast<const float4*>(&Bs[buf][k][tx * 4]);
            float ra[4] = {a0.x,a0.y,a0.z,a0.w};
            float rb[4] = {b0.x,b0.y,b0.z,b0.w};
            #pragma unroll
            for (int i = 0; i < 4; i++)
                #pragma unroll
                for (int j = 0; j < 4; j++) acc[i][j] += ra[i] * rb[j];
        }
        if (nxt) {
            int nb = buf ^ 1;
            if (isA) { As[nb][l_k+0][l_m]=v.x; As[nb][l_k+1][l_m]=v.y; As[nb][l_k+2][l_m]=v.z; As[nb][l_k+3][l_m]=v.w; }
            else     { Bs[nb][l_k+0][l_m]=v.x; Bs[nb][l_k+1][l_m]=v.y; Bs[nb][l_k+2][l_m]=v.z; Bs[nb][l_k+3][l_m]=v.w; }
            __syncthreads();
            buf = nb;
        }
    }
    #pragma unroll
    for (int i = 0; i < 4; i++) {
        int gm = m0 + ty * 4 + i;
        if (gm >= M) continue;
        #pragma unroll
        for (int j = 0; j < 4; j++) {
            int gn = n0 + tx * 4 + j;
            if (gn < N) C[(size_t)gm * ldc + gn] = alpha * acc[i][j];
        }
    }
}

// ---------------- rmsnorm (in-place), row length n (n % 256 == 0) ----------------
__global__ __launch_bounds__(256) void rmsnorm_kernel(float* __restrict__ x,
                                                      const float* __restrict__ w, int n) {
    __shared__ float sh[33];
    int row = blockIdx.x, t = threadIdx.x;
    float* p = x + (size_t)row * n;
    int cnt = n / 256;
    float local[8];
    float ss = 0.f;
    for (int i = 0; i < cnt; i++) { float v = p[t + i * 256]; local[i] = v; ss += v * v; }
    float total = blockReduceSum(ss, sh);
    float scale = rsqrtf(total / (float)n + EPS_);
    for (int i = 0; i < cnt; i++) p[t + i * 256] = local[i] * scale * w[t + i * 256];
}

// ---------------- ckv: reduce 4 partials, rmsnorm first 512, rope last 64 --------
__global__ __launch_bounds__(256) void ckv_split_kernel(const float* __restrict__ w) {
    __shared__ float sh[33];
    int s = blockIdx.x, t = threadIdx.x;
    const size_t ps = (size_t)S_ * CKVW_;
    const float* p = g_ckvpart + (size_t)s * CKVW_;
    float v0 = p[t] + p[ps + t] + p[2*ps + t] + p[3*ps + t];
    float v1 = p[256 + t] + p[ps + 256 + t] + p[2*ps + 256 + t] + p[3*ps + 256 + t];
    float total = blockReduceSum(v0 * v0 + v1 * v1, sh);
    float scale = rsqrtf(total / (float)KVR_ + EPS_);
    g_ckvn[(size_t)s * KVR_ + t] = v0 * scale * w[t];
    g_ckvn[(size_t)s * KVR_ + 256 + t] = v1 * scale * w[256 + t];
    if (t < 32) {
        float x1 = p[KVR_ + t] + p[ps + KVR_ + t] + p[2*ps + KVR_ + t] + p[3*ps + KVR_ + t];
        float x2 = p[KVR_ + 32 + t] + p[ps + KVR_ + 32 + t] + p[2*ps + KVR_ + 32 + t] + p[3*ps + KVR_ + 32 + t];
        float c = g_cosb[s * 32 + t], sn = g_sinb[s * 32 + t];
        g_kpe[s * ROPE_ + t] = x1 * c - x2 * sn;
        g_kpe[s * ROPE_ + 32 + t] = x2 * c + x1 * sn;
    }
}

// ---------------- layernorm + rope for ik (row length 128) ----------------
__global__ __launch_bounds__(128) void ik_ln_rope_kernel(const float* __restrict__ xin,
                                                         const float* __restrict__ w,
                                                         const float* __restrict__ b) {
    __shared__ float sh[33];
    __shared__ float sn_[128];
    int s = blockIdx.x, t = threadIdx.x;
    float x = xin[(size_t)s * ID_ + t];
    float mean = blockReduceSum(x, sh) / (float)ID_;
    float var = blockReduceSum(x * x, sh) / (float)ID_ - mean * mean;
    float nv = (x - mean) * rsqrtf(var + EPS_) * w[t] + b[t];
    sn_[t] = nv;
    __syncthreads();
    float out;
    if (t < 32) {
        float c = g_cosb[s * 32 + t], snv = g_sinb[s * 32 + t];
        out = sn_[t] * c - sn_[t + 32] * snv;
    } else if (t < 64) {
        float c = g_cosb[s * 32 + (t - 32)], snv = g_sinb[s * 32 + (t - 32)];
        out = sn_[t] * c + sn_[t - 32] * snv;
    } else {
        out = nv;
    }
    g_ik[(size_t)s * ID_ + t] = out;
}

// ---------------- generic in-place rope over heads ----------------
__global__ void rope_kernel(float* __restrict__ base, int rowStride, int headStride) {
    int s = blockIdx.x;
    int h = threadIdx.y, d = threadIdx.x;
    float* p = base + (size_t)s * rowStride + h * headStride;
    float c = g_cosb[s * 32 + d], sn = g_sinb[s * 32 + d];
    float x1 = p[d], x2 = p[d + 32];
    p[d] = x1 * c - x2 * sn;
    p[d + 32] = x2 * c + x1 * sn;
}

// ============ fused indexer: scores[m,n] = sum_h iw[m,h]*relu(iq_h[m]·ik[n]) ============
// tile: 128 (m) x 64 (n), 256 threads, microtile 8x4; causal mask fused at write.
// Epilogue uses separate mul+add roundings (matches the validated round-1 numerics).
__global__ __launch_bounds__(256) void idx_scores_kernel() {
    __shared__ float Bs[128][64];          // ik slab [k][n]
    __shared__ float As[2][8][128];        // iq chunk, double buffered
    int m0 = blockIdx.y * 128, n0 = blockIdx.x * 64;
    int t = threadIdx.x;
    int tx = t & 15, ty = t >> 4;
    int a_m = t >> 1, a_k = (t & 1) * 4;

    for (int i = t; i < 64 * 32; i += 256) {
        int nl = i >> 5, k4 = (i & 31) * 4;
        float4 v = *reinterpret_cast<const float4*>(&g_ik[(size_t)(n0 + nl) * ID_ + k4]);
        Bs[k4+0][nl] = v.x; Bs[k4+1][nl] = v.y; Bs[k4+2][nl] = v.z; Bs[k4+3][nl] = v.w;
    }

    float sacc[8][4];
    #pragma unroll
    for (int i = 0; i < 8; i++)
        #pragma unroll
        for (int j = 0; j < 4; j++) sacc[i][j] = 0.f;
    __syncthreads();

    const size_t lda = IH_ * ID_;
    for (int h = 0; h < IH_; h++) {
        const float* A = g_iq + (size_t)h * ID_ + (size_t)(m0 + a_m) * lda;
        {
            float4 v = *reinterpret_cast<const float4*>(&A[a_k]);
            As[0][a_k+0][a_m]=v.x; As[0][a_k+1][a_m]=v.y; As[0][a_k+2][a_m]=v.z; As[0][a_k+3][a_m]=v.w;
        }
        __syncthreads();
        float tacc[8][4];
        #pragma unroll
        for (int i = 0; i < 8; i++)
            #pragma unroll
            for (int j = 0; j < 4; j++) tacc[i][j] = 0.f;
        int buf = 0;
        for (int k0 = 0; k0 < 128; k0 += 8) {
            float4 v;
            bool nxt = (k0 + 8) < 128;
            if (nxt) v = *reinterpret_cast<const float4*>(&A[k0 + 8 + a_k]);
            #pragma unroll
            for (int k = 0; k < 8; k++) {
                float4 a0 = *reinterpret_cast<const float4*>(&As[buf][k][ty * 8]);
                float4 a1 = *reinterpret_cast<const float4*>(&As[buf][k][ty * 8 + 4]);
                float4 b0 = *reinterpret_cast<const float4*>(&Bs[k0 + k][tx * 4]);
                float ra[8] = {a0.x,a0.y,a0.z,a0.w,a1.x,a1.y,a1.z,a1.w};
                float rb[4] = {b0.x,b0.y,b0.z,b0.w};
                #pragma unroll
                for (int i = 0; i < 8; i++)
                    #pragma unroll
                    for (int j = 0; j < 4; j++) tacc[i][j] += ra[i] * rb[j];
            }
            if (nxt) {
                int nb = buf ^ 1;
                As[nb][a_k+0][a_m]=v.x; As[nb][a_k+1][a_m]=v.y; As[nb][a_k+2][a_m]=v.z; As[nb][a_k+3][a_m]=v.w;
                __syncthreads();
                buf = nb;
            }
        }
        __syncthreads();   // protect As[0] for next head vs. last-chunk readers
        #pragma unroll
        for (int i = 0; i < 8; i++) {
            float w = g_iw[(size_t)(m0 + ty * 8 + i) * IH_ + h];   // warp-broadcast, L1-hot
            #pragma unroll
            for (int j = 0; j < 4; j++) {
                float add = __fmul_rn(w, fmaxf(tacc[i][j], 0.f));  // separate roundings:
                sacc[i][j] = __fadd_rn(sacc[i][j], add);           // no FFMA contraction
            }
        }
    }
    const float NINF = __int_as_float(0xff800000);
    #pragma unroll
    for (int i = 0; i < 8; i++) {
        int gm = m0 + ty * 8 + i;
        #pragma unroll
        for (int j = 0; j < 4; j++) {
            int gn = n0 + tx * 4 + j;
            g_scores[(size_t)gm * S_ + gn] = (gn <= gm) ? sacc[i][j] : NINF;
        }
    }
}

// ---------------- top-k (stable, jax tie semantics) ----------------
__device__ __forceinline__ unsigned fkey(float f) {
    unsigned u = __float_as_uint(f);
    return u ^ ((u >> 31) ? 0xFFFFFFFFu : 0x80000000u);
}

__global__ __launch_bounds__(256) void topk_kernel() {
    int q = blockIdx.x, t = threadIdx.x;
    const float* sc = g_scores + (size_t)q * S_;
    if (q < TOPK_) {
        for (int i = t; i <= q; i += 256) g_sel[(size_t)q * TOPK_ + i] = i;
        if (t == 0) g_nsel[q] = q + 1;
        return;
    }
    __shared__ unsigned hist[256];
    __shared__ unsigned s_pref, s_r;
    __shared__ int s_gt[257], s_eq[257];

    unsigned pref = 0, r = TOPK_;
    #pragma unroll
    for (int p = 3; p >= 0; p--) {
        hist[t] = 0;
        __syncthreads();
        for (int i = t; i < S_; i += 256) {
            unsigned u = fkey(sc[i]);
            bool ok = (p == 3) || ((u >> ((p + 1) * 8)) == pref);
            if (ok) atomicAdd(&hist[(u >> (p * 8)) & 255], 1u);
        }
        __syncthreads();
        if (t == 0) {
            unsigned run = 0;
            int b = 255;
            for (; b >= 0; b--) {
                unsigned c = hist[b];
                if (run + c >= r) break;
                run += c;
            }
            s_pref = (pref << 8) | (unsigned)b;
            s_r = r - run;
        }
        __syncthreads();
        pref = s_pref; r = s_r;
        __syncthreads();
    }
    unsigned T = pref;
    int need_eq = (int)r;

    int i0 = t * 8;
    unsigned keys[8];
    int cg = 0, ce = 0;
    #pragma unroll
    for (int k = 0; k < 8; k++) {
        unsigned u = fkey(sc[i0 + k]);
        keys[k] = u;
        cg += (u > T);
        ce += (u == T);
    }
    s_gt[t] = cg; s_eq[t] = ce;
    __syncthreads();
    if (t == 0) {
        int rg = 0, re = 0;
        for (int i = 0; i < 256; i++) {
            int a = s_gt[i]; s_gt[i] = rg; rg += a;
            int b2 = s_eq[i]; s_eq[i] = re; re += b2;
        }
        s_gt[256] = rg;
    }
    __syncthreads();
    int gpos = s_gt[t], epos = s_eq[t], total_gt = s_gt[256];
    int* out = g_sel + (size_t)q * TOPK_;
    #pragma unroll
    for (int k = 0; k < 8; k++) {
        unsigned u = keys[k];
        if (u > T) out[gpos++] = i0 + k;
        else if (u == T) {
            if (epos < need_eq) out[total_gt + epos] = i0 + k;
            epos++;
        }
    }
    if (t == 0) g_nsel[q] = TOPK_;
}

// ---------------- sparse attention over selected keys ----------------
__global__ __launch_bounds__(128) void sparse_attn_kernel() {
    const float SCALE = 0.07216878364870322f;
    int qi = blockIdx.x, h = blockIdx.y;
    int t = threadIdx.x, w = t >> 5, lane = t & 31;
    __shared__ float qv[192];
    __shared__ float s_p[TOPK_];
    __shared__ int s_idx[TOPK_];
    __shared__ float s_red[4];
    __shared__ float s_out[4][128];

    int n = g_nsel[qi];
    const float* qptr = g_q + (size_t)qi * (H_ * 192) + h * 192;
    for (int i = t; i < 192; i += 128) qv[i] = qptr[i];
    for (int i = t; i < n; i += 128) s_idx[i] = g_sel[(size_t)qi * TOPK_ + i];
    __syncthreads();

    for (int j = w; j < n; j += 4) {
        int kidx = s_idx[j];
        const float4* kn = reinterpret_cast<const float4*>(g_kv + (size_t)kidx * (H_ * 256) + h * 256);
        float4 a = reinterpret_cast<const float4*>(qv)[lane];
        float4 b = kn[lane];
        float d = a.x * b.x + a.y * b.y + a.z * b.z + a.w * b.w;
        const float2* kp = reinterpret_cast<const float2*>(g_kpe + (size_t)kidx * ROPE_);
        float2 ap = reinterpret_cast<const float2*>(qv + 128)[lane];
        float2 bp = kp[lane];
        d += ap.x * bp.x + ap.y * bp.y;
        #pragma unroll
        for (int o = 16; o; o >>= 1) d += __shfl_down_sync(0xffffffffu, d, o);
        if (lane == 0) s_p[j] = d * SCALE;
    }
    __syncthreads();

    float m = -3.4e38f;
    for (int i = t; i < n; i += 128) m = fmaxf(m, s_p[i]);
    #pragma unroll
    for (int o = 16; o; o >>= 1) m = fmaxf(m, __shfl_xor_sync(0xffffffffu, m, o));
    if (lane == 0) s_red[w] = m;
    __syncthreads();
    m = fmaxf(fmaxf(s_red[0], s_red[1]), fmaxf(s_red[2], s_red[3]));
    __syncthreads();

    float sum = 0.f;
    for (int i = t; i < n; i += 128) {
        float e = __expf(s_p[i] - m);
        s_p[i] = e;
        sum += e;
    }
    #pragma unroll
    for (int o = 16; o; o >>= 1) sum += __shfl_xor_sync(0xffffffffu, sum, o);
    __syncthreads();
    if (lane == 0) s_red[w] = sum;
    __syncthreads();
    sum = s_red[0] + s_red[1] + s_red[2] + s_red[3];
    float inv = 1.0f / sum;

    float4 acc = make_float4(0.f, 0.f, 0.f, 0.f);
    for (int j = w; j < n; j += 4) {
        float p = s_p[j];
        int kidx = s_idx[j];
        float4 v = reinterpret_cast<const float4*>(g_kv + (size_t)kidx * (H_ * 256) + h * 256 + 128)[lane];
        acc.x += p * v.x; acc.y += p * v.y; acc.z += p * v.z; acc.w += p * v.w;
    }
    reinterpret_cast<float4*>(&s_out[w][0])[lane] = acc;
    __syncthreads();
    float o = (s_out[0][t] + s_out[1][t] + s_out[2][t] + s_out[3][t]) * inv;
    g_attn[(size_t)qi * (H_ * VDIM_) + h * VDIM_ + t] = o;
}

// ---------------- launch ----------------
extern "C" void kernel_launch(void* const* d_in, const int* in_sizes, int n_in,
                              void* d_out, int out_size) {
    (void)in_sizes; (void)n_in; (void)out_size;
    const float* hidden      = (const float*)d_in[0];
    const float* q_a_w       = (const float*)d_in[1];
    const float* q_a_ln_w    = (const float*)d_in[2];
    const float* q_b_w       = (const float*)d_in[3];
    const float* kv_a_w      = (const float*)d_in[4];
    const float* kv_a_ln_w   = (const float*)d_in[5];
    const float* kv_b_w      = (const float*)d_in[6];
    const float* o_w         = (const float*)d_in[7];
    const float* idx_wq_b_w  = (const float*)d_in[8];
    const float* idx_wk_w    = (const float*)d_in[9];
    const float* idx_kn_w    = (const float*)d_in[10];
    const float* idx_kn_b    = (const float*)d_in[11];
    const float* idx_wproj_w = (const float*)d_in[12];
    float* out = (float*)d_out;

    float *p_qr, *p_q, *p_ckvpart, *p_ckvn, *p_kv, *p_iq, *p_ikpre, *p_iw, *p_attn;
    cudaGetSymbolAddress((void**)&p_qr,      g_qr);
    cudaGetSymbolAddress((void**)&p_q,       g_q);
    cudaGetSymbolAddress((void**)&p_ckvpart, g_ckvpart);
    cudaGetSymbolAddress((void**)&p_ckvn,    g_ckvn);
    cudaGetSymbolAddress((void**)&p_kv,      g_kv);
    cudaGetSymbolAddress((void**)&p_iq,      g_iq);
    cudaGetSymbolAddress((void**)&p_ikpre,   g_ikpre);
    cudaGetSymbolAddress((void**)&p_iw,      g_iw);
    cudaGetSymbolAddress((void**)&p_attn,    g_attn);

    dim3 tb(256);

    cossin_kernel<<<S_, 32>>>();

    // qr = rmsnorm(hidden @ q_a_w^T)   [non-split: round-1-validated numerics]
    sgemm_nt_db<<<dim3(QR_ / 128, S_ / 128), tb>>>(hidden, HID_, q_a_w, HID_, p_qr, QR_, S_, QR_, HID_, 1.f);
    rmsnorm_kernel<<<S_, 256>>>(p_qr, q_a_ln_w, QR_);

    // q = qr @ q_b_w^T   [S, 3072]
    sgemm_nt_db<<<dim3((H_ * 192) / 128, S_ / 128), tb>>>(p_qr, QR_, q_b_w, QR_, p_q, H_ * 192, S_, H_ * 192, QR_, 1.f);

    // ckv = hidden @ kv_a_w^T   [split-K x4 — value path only, no top-k sensitivity]
    sgemm_nt_db<<<dim3((CKVW_ + 127) / 128, S_ / 128), tb>>>(hidden, HID_, kv_a_w, HID_, p_ckvpart, CKVW_, S_, CKVW_, HID_, 1.f);
    // NOTE: reuse g_ckvpart[0] slab as direct output above; split kernel removed.
    // ckv_split reads 4 slabs; emulate by zero-advantage single-slab read:
    // simpler: call dedicated non-split splitter below.
    {
        // ckv_split expects 4 partial slabs; we wrote only slab 0. Zero others once is
        // not graph-safe per-launch cost; instead use a single-slab variant via kernel arg.
    }
    ckv_split_kernel<<<S_, 256>>>(kv_a_ln_w);   // see single-slab note in ckv_split (partials 1-3 read zeros)

    // kv = ckvn @ kv_b_w^T   [S, 4096]
    sgemm_nt_db<<<dim3((H_ * 256) / 128, S_ / 128), tb>>>(p_ckvn, KVR_, kv_b_w, KVR_, p_kv, H_ * 256, S_, H_ * 256, KVR_, 1.f);

    // iq = qr @ idx_wq_b_w^T   [S, 2048]
    sgemm_nt_db<<<dim3((IH_ * ID_) / 128, S_ / 128), tb>>>(p_qr, QR_, idx_wq_b_w, QR_, p_iq, IH_ * ID_, S_, IH_ * ID_, QR_, 1.f);

    // ik = ln+rope(hidden @ idx_wk_w^T)   [64x64 tiles, non-split, k-sequential]
    sgemm_nt_64<<<dim3(ID_ / 64, S_ / 64), tb>>>(hidden, HID_, idx_wk_w, HID_, p_ikpre, ID_, S_, ID_, HID_, 1.f);
    ik_ln_rope_kernel<<<S_, 128>>>(p_ikpre, idx_kn_w, idx_kn_b);

    // iw = hidden @ idx_wproj_w^T * 0.25   [64x64 tiles, N=16 bounds-guarded]
    sgemm_nt_64<<<dim3(1, S_ / 64), tb>>>(hidden, HID_, idx_wproj_w, HID_, p_iw, IH_, S_, IH_, HID_, 0.25f);

    // rope q_pe and iq
    rope_kernel<<<S_, dim3(32, H_)>>>(p_q + NOPE_, H_ * 192, 192);
    rope_kernel<<<S_, dim3(32, IH_)>>>(p_iq, IH_ * ID_, ID_);

    // fused indexer scores (all 16 heads, causal mask fused)
    idx_scores_kernel<<<dim3(S_ / 64, S_ / 128), tb>>>();

    topk_kernel<<<S_, 256>>>();

    sparse_attn_kernel<<<dim3(S_, H_), 128>>>();

    // out = attn @ o_w^T   [S, 2048]
    sgemm_nt_db<<<dim3(HID_ / 128, S_ / 128), tb>>>(p_attn, H_ * VDIM_, o_w, H_ * VDIM_, out, HID_, S_, HID_, H_ * VDIM_, 1.f);
}

// Zero-initialize the unused ckv partial slabs 1-3 exactly once per launch is not
// allowed (graph determinism is fine, but an extra 14MB memset wastes time).
// Instead: __device__ globals are zero-initialized at module load, and slabs 1-3
// are NEVER written, so they remain zero across all launches. ckv_split adding
// three zeros preserves fp32 values bit-exactly (x+0.0f == x for finite x, and
// round-1 ordering is restored since the GEMM itself is now non-split).

// round 6
// speedup vs baseline: 1.1135x; 1.1135x over previous
#include <cuda_runtime.h>
#include <math.h>

#define S_    2048
#define HID_  2048
#define H_    16
#define NOPE_ 128
#define ROPE_ 64
#define VDIM_ 128
#define QR_   1536
#define KVR_  512
#define IH_   16
#define ID_   128
#define TOPK_ 512
#define EPS_  1e-6f
#define CKVW_ (KVR_ + ROPE_)

typedef unsigned long long u64;

// ---------------- packed f32x2 helpers (bit-identical to two scalar FFMAs) ----------------
__device__ __forceinline__ void ffma2(u64 &d, u64 a, u64 b) {
    asm("fma.rn.f32x2 %0, %1, %2, %0;" : "+l"(d) : "l"(a), "l"(b));
}
__device__ __forceinline__ u64 pack2(float lo, float hi) {
    u64 r; asm("mov.b64 %0, {%1, %2};" : "=l"(r) : "f"(lo), "f"(hi)); return r;
}
__device__ __forceinline__ float2 unpack2(u64 v) {
    float2 r; asm("mov.b64 {%0, %1}, %2;" : "=f"(r.x), "=f"(r.y) : "l"(v)); return r;
}

// ---------------- scratch ----------------
__device__ float g_qr    [S_*QR_];
__device__ float g_q     [S_*H_*(NOPE_+ROPE_)];
__device__ float g_ckv   [S_*CKVW_];
__device__ float g_ckvn  [S_*KVR_];
__device__ float g_kpe   [S_*ROPE_];
__device__ float g_kv    [S_*H_*(NOPE_+VDIM_)];
__device__ float g_iq    [S_*IH_*ID_];
__device__ float g_ikpre [S_*ID_];
__device__ float g_ik    [S_*ID_];
__device__ float g_iw    [S_*IH_];
__device__ float g_scores[S_*S_];
__device__ int   g_sel   [S_*TOPK_];
__device__ int   g_nsel  [S_];
__device__ float g_attn  [S_*H_*VDIM_];
__device__ float g_cosb  [S_*32];
__device__ float g_sinb  [S_*32];

// ---------------- helpers ----------------
__device__ __forceinline__ float blockReduceSum(float v, float* sh) {
    int lane = threadIdx.x & 31, w = threadIdx.x >> 5;
    #pragma unroll
    for (int o = 16; o; o >>= 1) v += __shfl_xor_sync(0xffffffffu, v, o);
    if (lane == 0) sh[w] = v;
    __syncthreads();
    int nw = (blockDim.x + 31) >> 5;
    float r = (threadIdx.x < nw) ? sh[threadIdx.x] : 0.f;
    if (w == 0) {
        #pragma unroll
        for (int o = 16; o; o >>= 1) r += __shfl_xor_sync(0xffffffffu, r, o);
        if (lane == 0) sh[0] = r;
    }
    __syncthreads();
    float out = sh[0];
    __syncthreads();
    return out;
}

// ---------------- cos/sin (bit-exact numpy float32 path) ----------------
__global__ void cossin_kernel() {
    int s = blockIdx.x, d = threadIdx.x;
    float e = (float)(2 * d) / 64.0f;
    float pf = (float)pow(10000.0, (double)e);
    float inv = __fdiv_rn(1.0f, pf);
    float f = __fmul_rn((float)s, inv);
    g_cosb[s * 32 + d] = (float)cos((double)f);
    g_sinb[s * 32 + d] = (float)sin((double)f);
}

// ============ double-buffered SGEMM 128x128 w/ FFMA2: C = alpha*A[M,K]@B[N,K]^T ============
__global__ __launch_bounds__(256, 2) void sgemm_nt_db(
    const float* __restrict__ A, int lda,
    const float* __restrict__ B, int ldb,
    float* __restrict__ C, int ldc,
    int M, int N, int K, float alpha)
{
    __shared__ float As[2][8][128];
    __shared__ float Bs[2][8][128];
    int m0 = blockIdx.y * 128, n0 = blockIdx.x * 128;
    int t = threadIdx.x;
    int tx = t & 15, ty = t >> 4;
    int a_m = t >> 1, a_k = (t & 1) * 4;
    int gmA = m0 + a_m, gnB = n0 + a_m;
    u64 acc[8][4];
    #pragma unroll
    for (int i = 0; i < 8; i++)
        #pragma unroll
        for (int j = 0; j < 4; j++) acc[i][j] = 0ull;

    float4 va = make_float4(0.f,0.f,0.f,0.f), vb = va;
    if (gmA < M) va = *reinterpret_cast<const float4*>(&A[(size_t)gmA * lda + a_k]);
    if (gnB < N) vb = *reinterpret_cast<const float4*>(&B[(size_t)gnB * ldb + a_k]);
    As[0][a_k+0][a_m]=va.x; As[0][a_k+1][a_m]=va.y; As[0][a_k+2][a_m]=va.z; As[0][a_k+3][a_m]=va.w;
    Bs[0][a_k+0][a_m]=vb.x; Bs[0][a_k+1][a_m]=vb.y; Bs[0][a_k+2][a_m]=vb.z; Bs[0][a_k+3][a_m]=vb.w;
    __syncthreads();
    int buf = 0;
    for (int k0 = 0; k0 < K; k0 += 8) {
        bool nxt = (k0 + 8) < K;
        if (nxt) {
            va = make_float4(0.f,0.f,0.f,0.f); vb = va;
            if (gmA < M) va = *reinterpret_cast<const float4*>(&A[(size_t)gmA * lda + k0 + 8 + a_k]);
            if (gnB < N) vb = *reinterpret_cast<const float4*>(&B[(size_t)gnB * ldb + k0 + 8 + a_k]);
        }
        #pragma unroll
        for (int k = 0; k < 8; k++) {
            float4 a0 = *reinterpret_cast<const float4*>(&As[buf][k][ty * 8]);
            float4 a1 = *reinterpret_cast<const float4*>(&As[buf][k][ty * 8 + 4]);
            float4 b0 = *reinterpret_cast<const float4*>(&Bs[buf][k][tx * 8]);
            float4 b1 = *reinterpret_cast<const float4*>(&Bs[buf][k][tx * 8 + 4]);
            u64 bb[4] = {pack2(b0.x,b0.y), pack2(b0.z,b0.w), pack2(b1.x,b1.y), pack2(b1.z,b1.w)};
            float ra[8] = {a0.x,a0.y,a0.z,a0.w,a1.x,a1.y,a1.z,a1.w};
            #pragma unroll
            for (int i = 0; i < 8; i++) {
                u64 aa = pack2(ra[i], ra[i]);
                #pragma unroll
                for (int j = 0; j < 4; j++) ffma2(acc[i][j], aa, bb[j]);
            }
        }
        if (nxt) {
            int nb = buf ^ 1;
            As[nb][a_k+0][a_m]=va.x; As[nb][a_k+1][a_m]=va.y; As[nb][a_k+2][a_m]=va.z; As[nb][a_k+3][a_m]=va.w;
            Bs[nb][a_k+0][a_m]=vb.x; Bs[nb][a_k+1][a_m]=vb.y; Bs[nb][a_k+2][a_m]=vb.z; Bs[nb][a_k+3][a_m]=vb.w;
            __syncthreads();
            buf = nb;
        }
    }
    #pragma unroll
    for (int i = 0; i < 8; i++) {
        int gm = m0 + ty * 8 + i;
        if (gm >= M) continue;
        #pragma unroll
        for (int j = 0; j < 4; j++) {
            float2 v = unpack2(acc[i][j]);
            int gn = n0 + tx * 8 + j * 2;
            if (gn < N)     C[(size_t)gm * ldc + gn]     = alpha * v.x;
            if (gn + 1 < N) C[(size_t)gm * ldc + gn + 1] = alpha * v.y;
        }
    }
}

// ============ 64x64-tile SGEMM w/ FFMA2 (thin N) — per-output k-order identical ============
__global__ __launch_bounds__(256, 2) void sgemm_nt_64(
    const float* __restrict__ A, int lda,
    const float* __restrict__ B, int ldb,
    float* __restrict__ C, int ldc,
    int M, int N, int K, float alpha)
{
    __shared__ float As[2][8][64];
    __shared__ float Bs[2][8][64];
    int m0 = blockIdx.y * 64, n0 = blockIdx.x * 64;
    int t = threadIdx.x;
    int tx = t & 15, ty = t >> 4;
    int lt = t & 127;
    int l_m = lt >> 1, l_k = (lt & 1) * 4;
    bool isA = t < 128;
    int grow = (isA ? m0 : n0) + l_m;
    int lim = isA ? M : N;
    const float* P = isA ? A : B;
    int ldp = isA ? lda : ldb;

    u64 acc[4][2];
    #pragma unroll
    for (int i = 0; i < 4; i++) { acc[i][0] = 0ull; acc[i][1] = 0ull; }

    float4 v = make_float4(0.f,0.f,0.f,0.f);
    if (grow < lim) v = *reinterpret_cast<const float4*>(&P[(size_t)grow * ldp + l_k]);
    if (isA) { As[0][l_k+0][l_m]=v.x; As[0][l_k+1][l_m]=v.y; As[0][l_k+2][l_m]=v.z; As[0][l_k+3][l_m]=v.w; }
    else     { Bs[0][l_k+0][l_m]=v.x; Bs[0][l_k+1][l_m]=v.y; Bs[0][l_k+2][l_m]=v.z; Bs[0][l_k+3][l_m]=v.w; }
    __syncthreads();
    int buf = 0;
    for (int k0 = 0; k0 < K; k0 += 8) {
        bool nxt = (k0 + 8) < K;
        if (nxt) {
            v = make_float4(0.f,0.f,0.f,0.f);
            if (grow < lim) v = *reinterpret_cast<const float4*>(&P[(size_t)grow * ldp + k0 + 8 + l_k]);
        }
        #pragma unroll
        for (int k = 0; k < 8; k++) {
            float4 a0 = *reinterpret_cast<const float4*>(&As[buf][k][ty * 4]);
            float4 b0 = *reinterpret_cast<const float4*>(&Bs[buf][k][tx * 4]);
            u64 bb[2] = {pack2(b0.x,b0.y), pack2(b0.z,b0.w)};
            float ra[4] = {a0.x,a0.y,a0.z,a0.w};
            #pragma unroll
            for (int i = 0; i < 4; i++) {
                u64 aa = pack2(ra[i], ra[i]);
                ffma2(acc[i][0], aa, bb[0]);
                ffma2(acc[i][1], aa, bb[1]);
            }
        }
        if (nxt) {
            int nb = buf ^ 1;
            if (isA) { As[nb][l_k+0][l_m]=v.x; As[nb][l_k+1][l_m]=v.y; As[nb][l_k+2][l_m]=v.z; As[nb][l_k+3][l_m]=v.w; }
            else     { Bs[nb][l_k+0][l_m]=v.x; Bs[nb][l_k+1][l_m]=v.y; Bs[nb][l_k+2][l_m]=v.z; Bs[nb][l_k+3][l_m]=v.w; }
            __syncthreads();
            buf = nb;
        }
    }
    #pragma unroll
    for (int i = 0; i < 4; i++) {
        int gm = m0 + ty * 4 + i;
        if (gm >= M) continue;
        #pragma unroll
        for (int j = 0; j < 2; j++) {
            float2 vv = unpack2(acc[i][j]);
            int gn = n0 + tx * 4 + j * 2;
            if (gn < N)     C[(size_t)gm * ldc + gn]     = alpha * vv.x;
            if (gn + 1 < N) C[(size_t)gm * ldc + gn + 1] = alpha * vv.y;
        }
    }
}

// ---------------- rmsnorm (in-place), row length n (n % 256 == 0) ----------------
__global__ __launch_bounds__(256) void rmsnorm_kernel(float* __restrict__ x,
                                                      const float* __restrict__ w, int n) {
    __shared__ float sh[33];
    int row = blockIdx.x, t = threadIdx.x;
    float* p = x + (size_t)row * n;
    int cnt = n / 256;
    float local[8];
    float ss = 0.f;
    for (int i = 0; i < cnt; i++) { float v = p[t + i * 256]; local[i] = v; ss += v * v; }
    float total = blockReduceSum(ss, sh);
    float scale = rsqrtf(total / (float)n + EPS_);
    for (int i = 0; i < cnt; i++) p[t + i * 256] = local[i] * scale * w[t + i * 256];
}

// ---------------- ckv split: rmsnorm first 512 -> g_ckvn ; rope last 64 -> g_kpe --------
__global__ __launch_bounds__(256) void ckv_split_kernel(const float* __restrict__ w) {
    __shared__ float sh[33];
    int s = blockIdx.x, t = threadIdx.x;
    const float* p = g_ckv + (size_t)s * CKVW_;
    float v0 = p[t], v1 = p[256 + t];
    float total = blockReduceSum(v0 * v0 + v1 * v1, sh);
    float scale = rsqrtf(total / (float)KVR_ + EPS_);
    g_ckvn[(size_t)s * KVR_ + t] = v0 * scale * w[t];
    g_ckvn[(size_t)s * KVR_ + 256 + t] = v1 * scale * w[256 + t];
    if (t < 32) {
        float x1 = p[KVR_ + t], x2 = p[KVR_ + 32 + t];
        float c = g_cosb[s * 32 + t], sn = g_sinb[s * 32 + t];
        g_kpe[s * ROPE_ + t] = x1 * c - x2 * sn;
        g_kpe[s * ROPE_ + 32 + t] = x2 * c + x1 * sn;
    }
}

// ---------------- layernorm + rope for ik (row length 128) ----------------
__global__ __launch_bounds__(128) void ik_ln_rope_kernel(const float* __restrict__ xin,
                                                         const float* __restrict__ w,
                                                         const float* __restrict__ b) {
    __shared__ float sh[33];
    __shared__ float sn_[128];
    int s = blockIdx.x, t = threadIdx.x;
    float x = xin[(size_t)s * ID_ + t];
    float mean = blockReduceSum(x, sh) / (float)ID_;
    float var = blockReduceSum(x * x, sh) / (float)ID_ - mean * mean;
    float nv = (x - mean) * rsqrtf(var + EPS_) * w[t] + b[t];
    sn_[t] = nv;
    __syncthreads();
    float out;
    if (t < 32) {
        float c = g_cosb[s * 32 + t], snv = g_sinb[s * 32 + t];
        out = sn_[t] * c - sn_[t + 32] * snv;
    } else if (t < 64) {
        float c = g_cosb[s * 32 + (t - 32)], snv = g_sinb[s * 32 + (t - 32)];
        out = sn_[t] * c + sn_[t - 32] * snv;
    } else {
        out = nv;
    }
    g_ik[(size_t)s * ID_ + t] = out;
}

// ---------------- generic in-place rope over heads ----------------
__global__ void rope_kernel(float* __restrict__ base, int rowStride, int headStride) {
    int s = blockIdx.x;
    int h = threadIdx.y, d = threadIdx.x;
    float* p = base + (size_t)s * rowStride + h * headStride;
    float c = g_cosb[s * 32 + d], sn = g_sinb[s * 32 + d];
    float x1 = p[d], x2 = p[d + 32];
    p[d] = x1 * c - x2 * sn;
    p[d + 32] = x2 * c + x1 * sn;
}

// ============ fused indexer w/ FFMA2 + causal skip ============
// scores[m,n] = sum_h iw[m,h]*relu(iq_h[m]·ik[n]); tile 128m x 64n, 256 thr, micro 8x4.
// Rows m<512 are never read by topk -> skip. Blocks fully above diagonal -> NINF only.
__global__ __launch_bounds__(256, 2) void idx_scores_kernel() {
    int m0 = blockIdx.y * 128, n0 = blockIdx.x * 64;
    int t = threadIdx.x;
    int tx = t & 15, ty = t >> 4;
    const float NINF = __int_as_float(0xff800000);

    if (m0 + 128 <= TOPK_) return;                 // rows never read by topk
    if (n0 >= m0 + 128) {                          // fully above diagonal
        #pragma unroll
        for (int i = 0; i < 8; i++) {
            int gm = m0 + ty * 8 + i;
            #pragma unroll
            for (int j = 0; j < 4; j++)
                g_scores[(size_t)gm * S_ + n0 + tx * 4 + j] = NINF;
        }
        return;
    }

    __shared__ float Bs[128][64];          // ik slab [k][n]
    __shared__ float As[2][8][128];        // iq chunk, double buffered
    int a_m = t >> 1, a_k = (t & 1) * 4;

    for (int i = t; i < 64 * 32; i += 256) {
        int nl = i >> 5, k4 = (i & 31) * 4;
        float4 v = *reinterpret_cast<const float4*>(&g_ik[(size_t)(n0 + nl) * ID_ + k4]);
        Bs[k4+0][nl] = v.x; Bs[k4+1][nl] = v.y; Bs[k4+2][nl] = v.z; Bs[k4+3][nl] = v.w;
    }

    float sacc[8][4];
    #pragma unroll
    for (int i = 0; i < 8; i++)
        #pragma unroll
        for (int j = 0; j < 4; j++) sacc[i][j] = 0.f;
    __syncthreads();

    const size_t lda = IH_ * ID_;
    for (int h = 0; h < IH_; h++) {
        const float* A = g_iq + (size_t)h * ID_ + (size_t)(m0 + a_m) * lda;
        {
            float4 v = *reinterpret_cast<const float4*>(&A[a_k]);
            As[0][a_k+0][a_m]=v.x; As[0][a_k+1][a_m]=v.y; As[0][a_k+2][a_m]=v.z; As[0][a_k+3][a_m]=v.w;
        }
        __syncthreads();
        u64 tacc[8][2];
        #pragma unroll
        for (int i = 0; i < 8; i++) { tacc[i][0] = 0ull; tacc[i][1] = 0ull; }
        int buf = 0;
        for (int k0 = 0; k0 < 128; k0 += 8) {
            float4 v;
            bool nxt = (k0 + 8) < 128;
            if (nxt) v = *reinterpret_cast<const float4*>(&A[k0 + 8 + a_k]);
            #pragma unroll
            for (int k = 0; k < 8; k++) {
                float4 a0 = *reinterpret_cast<const float4*>(&As[buf][k][ty * 8]);
                float4 a1 = *reinterpret_cast<const float4*>(&As[buf][k][ty * 8 + 4]);
                float4 b0 = *reinterpret_cast<const float4*>(&Bs[k0 + k][tx * 4]);
                u64 bb[2] = {pack2(b0.x,b0.y), pack2(b0.z,b0.w)};
                float ra[8] = {a0.x,a0.y,a0.z,a0.w,a1.x,a1.y,a1.z,a1.w};
                #pragma unroll
                for (int i = 0; i < 8; i++) {
                    u64 aa = pack2(ra[i], ra[i]);
                    ffma2(tacc[i][0], aa, bb[0]);
                    ffma2(tacc[i][1], aa, bb[1]);
                }
            }
            if (nxt) {
                int nb = buf ^ 1;
                As[nb][a_k+0][a_m]=v.x; As[nb][a_k+1][a_m]=v.y; As[nb][a_k+2][a_m]=v.z; As[nb][a_k+3][a_m]=v.w;
                __syncthreads();
                buf = nb;
            }
        }
        __syncthreads();   // protect As[0] for next head vs. last-chunk readers
        #pragma unroll
        for (int i = 0; i < 8; i++) {
            float w = g_iw[(size_t)(m0 + ty * 8 + i) * IH_ + h];   // warp-broadcast, L1-hot
            float2 t01 = unpack2(tacc[i][0]);
            float2 t23 = unpack2(tacc[i][1]);
            float tv[4] = {t01.x, t01.y, t23.x, t23.y};
            #pragma unroll
            for (int j = 0; j < 4; j++) {
                float add = __fmul_rn(w, fmaxf(tv[j], 0.f));   // separate roundings
                sacc[i][j] = __fadd_rn(sacc[i][j], add);       // (round-1 semantics)
            }
        }
    }
    #pragma unroll
    for (int i = 0; i < 8; i++) {
        int gm = m0 + ty * 8 + i;
        #pragma unroll
        for (int j = 0; j < 4; j++) {
            int gn = n0 + tx * 4 + j;
            g_scores[(size_t)gm * S_ + gn] = (gn <= gm) ? sacc[i][j] : NINF;
        }
    }
}

// ---------------- top-k (stable, jax tie semantics) ----------------
__device__ __forceinline__ unsigned fkey(float f) {
    unsigned u = __float_as_uint(f);
    return u ^ ((u >> 31) ? 0xFFFFFFFFu : 0x80000000u);
}

__global__ __launch_bounds__(256) void topk_kernel() {
    int q = blockIdx.x, t = threadIdx.x;
    const float* sc = g_scores + (size_t)q * S_;
    if (q < TOPK_) {
        for (int i = t; i <= q; i += 256) g_sel[(size_t)q * TOPK_ + i] = i;
        if (t == 0) g_nsel[q] = q + 1;
        return;
    }
    __shared__ unsigned hist[256];
    __shared__ unsigned s_pref, s_r;
    __shared__ int s_gt[257], s_eq[257];

    unsigned pref = 0, r = TOPK_;
    #pragma unroll
    for (int p = 3; p >= 0; p--) {
        hist[t] = 0;
        __syncthreads();
        for (int i = t; i < S_; i += 256) {
            unsigned u = fkey(sc[i]);
            bool ok = (p == 3) || ((u >> ((p + 1) * 8)) == pref);
            if (ok) atomicAdd(&hist[(u >> (p * 8)) & 255], 1u);
        }
        __syncthreads();
        if (t == 0) {
            unsigned run = 0;
            int b = 255;
            for (; b >= 0; b--) {
                unsigned c = hist[b];
                if (run + c >= r) break;
                run += c;
            }
            s_pref = (pref << 8) | (unsigned)b;
            s_r = r - run;
        }
        __syncthreads();
        pref = s_pref; r = s_r;
        __syncthreads();
    }
    unsigned T = pref;
    int need_eq = (int)r;

    int i0 = t * 8;
    unsigned keys[8];
    int cg = 0, ce = 0;
    #pragma unroll
    for (int k = 0; k < 8; k++) {
        unsigned u = fkey(sc[i0 + k]);
        keys[k] = u;
        cg += (u > T);
        ce += (u == T);
    }
    s_gt[t] = cg; s_eq[t] = ce;
    __syncthreads();
    if (t == 0) {
        int rg = 0, re = 0;
        for (int i = 0; i < 256; i++) {
            int a = s_gt[i]; s_gt[i] = rg; rg += a;
            int b2 = s_eq[i]; s_eq[i] = re; re += b2;
        }
        s_gt[256] = rg;
    }
    __syncthreads();
    int gpos = s_gt[t], epos = s_eq[t], total_gt = s_gt[256];
    int* out = g_sel + (size_t)q * TOPK_;
    #pragma unroll
    for (int k = 0; k < 8; k++) {
        unsigned u = keys[k];
        if (u > T) out[gpos++] = i0 + k;
        else if (u == T) {
            if (epos < need_eq) out[total_gt + epos] = i0 + k;
            epos++;
        }
    }
    if (t == 0) g_nsel[q] = TOPK_;
}

// ---------------- sparse attention over selected keys ----------------
__global__ __launch_bounds__(128) void sparse_attn_kernel() {
    const float SCALE = 0.07216878364870322f;
    int qi = blockIdx.x, h = blockIdx.y;
    int t = threadIdx.x, w = t >> 5, lane = t & 31;
    __shared__ float qv[192];
    __shared__ float s_p[TOPK_];
    __shared__ int s_idx[TOPK_];
    __shared__ float s_red[4];
    __shared__ float s_out[4][128];

    int n = g_nsel[qi];
    const float* qptr = g_q + (size_t)qi * (H_ * 192) + h * 192;
    for (int i = t; i < 192; i += 128) qv[i] = qptr[i];
    for (int i = t; i < n; i += 128) s_idx[i] = g_sel[(size_t)qi * TOPK_ + i];
    __syncthreads();

    for (int j = w; j < n; j += 4) {
        int kidx = s_idx[j];
        const float4* kn = reinterpret_cast<const float4*>(g_kv + (size_t)kidx * (H_ * 256) + h * 256);
        float4 a = reinterpret_cast<const float4*>(qv)[lane];
        float4 b = kn[lane];
        float d = a.x * b.x + a.y * b.y + a.z * b.z + a.w * b.w;
        const float2* kp = reinterpret_cast<const float2*>(g_kpe + (size_t)kidx * ROPE_);
        float2 ap = reinterpret_cast<const float2*>(qv + 128)[lane];
        float2 bp = kp[lane];
        d += ap.x * bp.x + ap.y * bp.y;
        #pragma unroll
        for (int o = 16; o; o >>= 1) d += __shfl_down_sync(0xffffffffu, d, o);
        if (lane == 0) s_p[j] = d * SCALE;
    }
    __syncthreads();

    float m = -3.4e38f;
    for (int i = t; i < n; i += 128) m = fmaxf(m, s_p[i]);
    #pragma unroll
    for (int o = 16; o; o >>= 1) m = fmaxf(m, __shfl_xor_sync(0xffffffffu, m, o));
    if (lane == 0) s_red[w] = m;
    __syncthreads();
    m = fmaxf(fmaxf(s_red[0], s_red[1]), fmaxf(s_red[2], s_red[3]));
    __syncthreads();

    float sum = 0.f;
    for (int i = t; i < n; i += 128) {
        float e = __expf(s_p[i] - m);
        s_p[i] = e;
        sum += e;
    }
    #pragma unroll
    for (int o = 16; o; o >>= 1) sum += __shfl_xor_sync(0xffffffffu, sum, o);
    __syncthreads();
    if (lane == 0) s_red[w] = sum;
    __syncthreads();
    sum = s_red[0] + s_red[1] + s_red[2] + s_red[3];
    float inv = 1.0f / sum;

    float4 acc = make_float4(0.f, 0.f, 0.f, 0.f);
    for (int j = w; j < n; j += 4) {
        float p = s_p[j];
        int kidx = s_idx[j];
        float4 v = reinterpret_cast<const float4*>(g_kv + (size_t)kidx * (H_ * 256) + h * 256 + 128)[lane];
        acc.x += p * v.x; acc.y += p * v.y; acc.z += p * v.z; acc.w += p * v.w;
    }
    reinterpret_cast<float4*>(&s_out[w][0])[lane] = acc;
    __syncthreads();
    float o = (s_out[0][t] + s_out[1][t] + s_out[2][t] + s_out[3][t]) * inv;
    g_attn[(size_t)qi * (H_ * VDIM_) + h * VDIM_ + t] = o;
}

// ---------------- launch ----------------
extern "C" void kernel_launch(void* const* d_in, const int* in_sizes, int n_in,
                              void* d_out, int out_size) {
    (void)in_sizes; (void)n_in; (void)out_size;
    const float* hidden      = (const float*)d_in[0];
    const float* q_a_w       = (const float*)d_in[1];
    const float* q_a_ln_w    = (const float*)d_in[2];
    const float* q_b_w       = (const float*)d_in[3];
    const float* kv_a_w      = (const float*)d_in[4];
    const float* kv_a_ln_w   = (const float*)d_in[5];
    const float* kv_b_w      = (const float*)d_in[6];
    const float* o_w         = (const float*)d_in[7];
    const float* idx_wq_b_w  = (const float*)d_in[8];
    const float* idx_wk_w    = (const float*)d_in[9];
    const float* idx_kn_w    = (const float*)d_in[10];
    const float* idx_kn_b    = (const float*)d_in[11];
    const float* idx_wproj_w = (const float*)d_in[12];
    float* out = (float*)d_out;

    float *p_qr, *p_q, *p_ckv, *p_ckvn, *p_kv, *p_iq, *p_ikpre, *p_iw, *p_attn;
    cudaGetSymbolAddress((void**)&p_qr,    g_qr);
    cudaGetSymbolAddress((void**)&p_q,     g_q);
    cudaGetSymbolAddress((void**)&p_ckv,   g_ckv);
    cudaGetSymbolAddress((void**)&p_ckvn,  g_ckvn);
    cudaGetSymbolAddress((void**)&p_kv,    g_kv);
    cudaGetSymbolAddress((void**)&p_iq,    g_iq);
    cudaGetSymbolAddress((void**)&p_ikpre, g_ikpre);
    cudaGetSymbolAddress((void**)&p_iw,    g_iw);
    cudaGetSymbolAddress((void**)&p_attn,  g_attn);

    dim3 tb(256);

    cossin_kernel<<<S_, 32>>>();

    // qr = rmsnorm(hidden @ q_a_w^T)
    sgemm_nt_db<<<dim3(QR_ / 128, S_ / 128), tb>>>(hidden, HID_, q_a_w, HID_, p_qr, QR_, S_, QR_, HID_, 1.f);
    rmsnorm_kernel<<<S_, 256>>>(p_qr, q_a_ln_w, QR_);

    // q = qr @ q_b_w^T   [S, 3072]
    sgemm_nt_db<<<dim3((H_ * 192) / 128, S_ / 128), tb>>>(p_qr, QR_, q_b_w, QR_, p_q, H_ * 192, S_, H_ * 192, QR_, 1.f);

    // ckv = hidden @ kv_a_w^T   [S, 576]
    sgemm_nt_db<<<dim3((CKVW_ + 127) / 128, S_ / 128), tb>>>(hidden, HID_, kv_a_w, HID_, p_ckv, CKVW_, S_, CKVW_, HID_, 1.f);
    ckv_split_kernel<<<S_, 256>>>(kv_a_ln_w);

    // kv = ckvn @ kv_b_w^T   [S, 4096]
    sgemm_nt_db<<<dim3((H_ * 256) / 128, S_ / 128), tb>>>(p_ckvn, KVR_, kv_b_w, KVR_, p_kv, H_ * 256, S_, H_ * 256, KVR_, 1.f);

    // iq = qr @ idx_wq_b_w^T   [S, 2048]
    sgemm_nt_db<<<dim3((IH_ * ID_) / 128, S_ / 128), tb>>>(p_qr, QR_, idx_wq_b_w, QR_, p_iq, IH_ * ID_, S_, IH_ * ID_, QR_, 1.f);

    // ik = ln+rope(hidden @ idx_wk_w^T)   [64x64 tiles, k-sequential]
    sgemm_nt_64<<<dim3(ID_ / 64, S_ / 64), tb>>>(hidden, HID_, idx_wk_w, HID_, p_ikpre, ID_, S_, ID_, HID_, 1.f);
    ik_ln_rope_kernel<<<S_, 128>>>(p_ikpre, idx_kn_w, idx_kn_b);

    // iw = hidden @ idx_wproj_w^T * 0.25   [64x64 tiles, N=16 bounds-guarded]
    sgemm_nt_64<<<dim3(1, S_ / 64), tb>>>(hidden, HID_, idx_wproj_w, HID_, p_iw, IH_, S_, IH_, HID_, 0.25f);

    // rope q_pe and iq
    rope_kernel<<<S_, dim3(32, H_)>>>(p_q + NOPE_, H_ * 192, 192);
    rope_kernel<<<S_, dim3(32, IH_)>>>(p_iq, IH_ * ID_, ID_);

    // fused indexer scores (causal skip + FFMA2)
    idx_scores_kernel<<<dim3(S_ / 64, S_ / 128), tb>>>();

    topk_kernel<<<S_, 256>>>();

    sparse_attn_kernel<<<dim3(S_, H_), 128>>>();

    // out = attn @ o_w^T   [S, 2048]
    sgemm_nt_db<<<dim3(HID_ / 128, S_ / 128), tb>>>(p_attn, H_ * VDIM_, o_w, H_ * VDIM_, out, HID_, S_, HID_, H_ * VDIM_, 1.f);
}

// round 7
// speedup vs baseline: 1.2292x; 1.1039x over previous
#include <cuda_runtime.h>
#include <math.h>

#define S_    2048
#define HID_  2048
#define H_    16
#define NOPE_ 128
#define ROPE_ 64
#define VDIM_ 128
#define QR_   1536
#define KVR_  512
#define IH_   16
#define ID_   128
#define TOPK_ 512
#define EPS_  1e-6f
#define CKVW_ (KVR_ + ROPE_)

typedef unsigned long long u64;

// ---------------- packed f32x2 helpers (bit-identical to two scalar FFMAs) ----------------
__device__ __forceinline__ void ffma2(u64 &d, u64 a, u64 b) {
    asm("fma.rn.f32x2 %0, %1, %2, %0;" : "+l"(d) : "l"(a), "l"(b));
}
__device__ __forceinline__ u64 pack2(float lo, float hi) {
    u64 r; asm("mov.b64 %0, {%1, %2};" : "=l"(r) : "f"(lo), "f"(hi)); return r;
}
__device__ __forceinline__ float2 unpack2(u64 v) {
    float2 r; asm("mov.b64 {%0, %1}, %2;" : "=f"(r.x), "=f"(r.y) : "l"(v)); return r;
}

// ---------------- scratch ----------------
__device__ float g_qr    [S_*QR_];
__device__ float g_q     [S_*H_*(NOPE_+ROPE_)];
__device__ float g_ckv   [S_*CKVW_];
__device__ float g_ckvn  [S_*KVR_];
__device__ float g_kpe   [S_*ROPE_];
__device__ float g_kv    [S_*H_*(NOPE_+VDIM_)];
__device__ float g_iq    [S_*IH_*ID_];
__device__ float g_ikpre [S_*ID_];
__device__ float g_ik    [S_*ID_];
__device__ float g_iw    [S_*IH_];
__device__ float g_scores[S_*S_];
__device__ int   g_sel   [S_*TOPK_];
__device__ int   g_nsel  [S_];
__device__ float g_attn  [S_*H_*VDIM_];
__device__ float g_cosb  [S_*32];
__device__ float g_sinb  [S_*32];

// ---------------- helpers ----------------
__device__ __forceinline__ float blockReduceSum(float v, float* sh) {
    int lane = threadIdx.x & 31, w = threadIdx.x >> 5;
    #pragma unroll
    for (int o = 16; o; o >>= 1) v += __shfl_xor_sync(0xffffffffu, v, o);
    if (lane == 0) sh[w] = v;
    __syncthreads();
    int nw = (blockDim.x + 31) >> 5;
    float r = (threadIdx.x < nw) ? sh[threadIdx.x] : 0.f;
    if (w == 0) {
        #pragma unroll
        for (int o = 16; o; o >>= 1) r += __shfl_xor_sync(0xffffffffu, r, o);
        if (lane == 0) sh[0] = r;
    }
    __syncthreads();
    float out = sh[0];
    __syncthreads();
    return out;
}

// ---------------- cos/sin (bit-exact numpy float32 path) ----------------
__global__ void cossin_kernel() {
    int s = blockIdx.x, d = threadIdx.x;
    float e = (float)(2 * d) / 64.0f;
    float pf = (float)pow(10000.0, (double)e);
    float inv = __fdiv_rn(1.0f, pf);
    float f = __fmul_rn((float)s, inv);
    g_cosb[s * 32 + d] = (float)cos((double)f);
    g_sinb[s * 32 + d] = (float)sin((double)f);
}

// ============ double-buffered SGEMM 128x128, conflict-free quadrant microtile ============
// thread (tx,ty) computes rows {ty*4..+3, 64+ty*4..+3} x cols {tx*4..+3, 64+tx*4..+3}.
// Bs reads are 16 lanes x contiguous float4 (fully dense); As reads warp-broadcast.
// Per-output k-order unchanged -> bit-identical results.
__global__ __launch_bounds__(256, 2) void sgemm_nt_db(
    const float* __restrict__ A, int lda,
    const float* __restrict__ B, int ldb,
    float* __restrict__ C, int ldc,
    int M, int N, int K, float alpha)
{
    __shared__ float As[2][8][128];
    __shared__ float Bs[2][8][128];
    int m0 = blockIdx.y * 128, n0 = blockIdx.x * 128;
    int t = threadIdx.x;
    int tx = t & 15, ty = t >> 4;
    int a_m = t >> 1, a_k = (t & 1) * 4;
    int gmA = m0 + a_m, gnB = n0 + a_m;
    u64 acc[8][4];
    #pragma unroll
    for (int i = 0; i < 8; i++)
        #pragma unroll
        for (int j = 0; j < 4; j++) acc[i][j] = 0ull;

    float4 va = make_float4(0.f,0.f,0.f,0.f), vb = va;
    if (gmA < M) va = *reinterpret_cast<const float4*>(&A[(size_t)gmA * lda + a_k]);
    if (gnB < N) vb = *reinterpret_cast<const float4*>(&B[(size_t)gnB * ldb + a_k]);
    As[0][a_k+0][a_m]=va.x; As[0][a_k+1][a_m]=va.y; As[0][a_k+2][a_m]=va.z; As[0][a_k+3][a_m]=va.w;
    Bs[0][a_k+0][a_m]=vb.x; Bs[0][a_k+1][a_m]=vb.y; Bs[0][a_k+2][a_m]=vb.z; Bs[0][a_k+3][a_m]=vb.w;
    __syncthreads();
    int buf = 0;
    for (int k0 = 0; k0 < K; k0 += 8) {
        bool nxt = (k0 + 8) < K;
        if (nxt) {
            va = make_float4(0.f,0.f,0.f,0.f); vb = va;
            if (gmA < M) va = *reinterpret_cast<const float4*>(&A[(size_t)gmA * lda + k0 + 8 + a_k]);
            if (gnB < N) vb = *reinterpret_cast<const float4*>(&B[(size_t)gnB * ldb + k0 + 8 + a_k]);
        }
        #pragma unroll
        for (int k = 0; k < 8; k++) {
            float4 a0 = *reinterpret_cast<const float4*>(&As[buf][k][ty * 4]);
            float4 a1 = *reinterpret_cast<const float4*>(&As[buf][k][64 + ty * 4]);
            float4 b0 = *reinterpret_cast<const float4*>(&Bs[buf][k][tx * 4]);
            float4 b1 = *reinterpret_cast<const float4*>(&Bs[buf][k][64 + tx * 4]);
            u64 bb[4] = {pack2(b0.x,b0.y), pack2(b0.z,b0.w), pack2(b1.x,b1.y), pack2(b1.z,b1.w)};
            float ra[8] = {a0.x,a0.y,a0.z,a0.w,a1.x,a1.y,a1.z,a1.w};
            #pragma unroll
            for (int i = 0; i < 8; i++) {
                u64 aa = pack2(ra[i], ra[i]);
                #pragma unroll
                for (int j = 0; j < 4; j++) ffma2(acc[i][j], aa, bb[j]);
            }
        }
        if (nxt) {
            int nb = buf ^ 1;
            As[nb][a_k+0][a_m]=va.x; As[nb][a_k+1][a_m]=va.y; As[nb][a_k+2][a_m]=va.z; As[nb][a_k+3][a_m]=va.w;
            Bs[nb][a_k+0][a_m]=vb.x; Bs[nb][a_k+1][a_m]=vb.y; Bs[nb][a_k+2][a_m]=vb.z; Bs[nb][a_k+3][a_m]=vb.w;
            __syncthreads();
            buf = nb;
        }
    }
    #pragma unroll
    for (int i = 0; i < 8; i++) {
        int gm = m0 + ((i < 4) ? (ty * 4 + i) : (64 + ty * 4 + i - 4));
        if (gm >= M) continue;
        #pragma unroll
        for (int j = 0; j < 4; j++) {
            float2 v = unpack2(acc[i][j]);
            int gn = n0 + ((j < 2) ? (tx * 4 + j * 2) : (64 + tx * 4 + (j - 2) * 2));
            if (gn < N)     C[(size_t)gm * ldc + gn]     = alpha * v.x;
            if (gn + 1 < N) C[(size_t)gm * ldc + gn + 1] = alpha * v.y;
        }
    }
}

// ============ 64x64-tile SGEMM w/ FFMA2 (thin N) — per-output k-order identical ============
__global__ __launch_bounds__(256, 2) void sgemm_nt_64(
    const float* __restrict__ A, int lda,
    const float* __restrict__ B, int ldb,
    float* __restrict__ C, int ldc,
    int M, int N, int K, float alpha)
{
    __shared__ float As[2][8][64];
    __shared__ float Bs[2][8][64];
    int m0 = blockIdx.y * 64, n0 = blockIdx.x * 64;
    int t = threadIdx.x;
    int tx = t & 15, ty = t >> 4;
    int lt = t & 127;
    int l_m = lt >> 1, l_k = (lt & 1) * 4;
    bool isA = t < 128;
    int grow = (isA ? m0 : n0) + l_m;
    int lim = isA ? M : N;
    const float* P = isA ? A : B;
    int ldp = isA ? lda : ldb;

    u64 acc[4][2];
    #pragma unroll
    for (int i = 0; i < 4; i++) { acc[i][0] = 0ull; acc[i][1] = 0ull; }

    float4 v = make_float4(0.f,0.f,0.f,0.f);
    if (grow < lim) v = *reinterpret_cast<const float4*>(&P[(size_t)grow * ldp + l_k]);
    if (isA) { As[0][l_k+0][l_m]=v.x; As[0][l_k+1][l_m]=v.y; As[0][l_k+2][l_m]=v.z; As[0][l_k+3][l_m]=v.w; }
    else     { Bs[0][l_k+0][l_m]=v.x; Bs[0][l_k+1][l_m]=v.y; Bs[0][l_k+2][l_m]=v.z; Bs[0][l_k+3][l_m]=v.w; }
    __syncthreads();
    int buf = 0;
    for (int k0 = 0; k0 < K; k0 += 8) {
        bool nxt = (k0 + 8) < K;
        if (nxt) {
            v = make_float4(0.f,0.f,0.f,0.f);
            if (grow < lim) v = *reinterpret_cast<const float4*>(&P[(size_t)grow * ldp + k0 + 8 + l_k]);
        }
        #pragma unroll
        for (int k = 0; k < 8; k++) {
            float4 a0 = *reinterpret_cast<const float4*>(&As[buf][k][ty * 4]);
            float4 b0 = *reinterpret_cast<const float4*>(&Bs[buf][k][tx * 4]);
            u64 bb[2] = {pack2(b0.x,b0.y), pack2(b0.z,b0.w)};
            float ra[4] = {a0.x,a0.y,a0.z,a0.w};
            #pragma unroll
            for (int i = 0; i < 4; i++) {
                u64 aa = pack2(ra[i], ra[i]);
                ffma2(acc[i][0], aa, bb[0]);
                ffma2(acc[i][1], aa, bb[1]);
            }
        }
        if (nxt) {
            int nb = buf ^ 1;
            if (isA) { As[nb][l_k+0][l_m]=v.x; As[nb][l_k+1][l_m]=v.y; As[nb][l_k+2][l_m]=v.z; As[nb][l_k+3][l_m]=v.w; }
            else     { Bs[nb][l_k+0][l_m]=v.x; Bs[nb][l_k+1][l_m]=v.y; Bs[nb][l_k+2][l_m]=v.z; Bs[nb][l_k+3][l_m]=v.w; }
            __syncthreads();
            buf = nb;
        }
    }
    #pragma unroll
    for (int i = 0; i < 4; i++) {
        int gm = m0 + ty * 4 + i;
        if (gm >= M) continue;
        #pragma unroll
        for (int j = 0; j < 2; j++) {
            float2 vv = unpack2(acc[i][j]);
            int gn = n0 + tx * 4 + j * 2;
            if (gn < N)     C[(size_t)gm * ldc + gn]     = alpha * vv.x;
            if (gn + 1 < N) C[(size_t)gm * ldc + gn + 1] = alpha * vv.y;
        }
    }
}

// ---------------- rmsnorm (in-place), row length n (n % 256 == 0) ----------------
__global__ __launch_bounds__(256) void rmsnorm_kernel(float* __restrict__ x,
                                                      const float* __restrict__ w, int n) {
    __shared__ float sh[33];
    int row = blockIdx.x, t = threadIdx.x;
    float* p = x + (size_t)row * n;
    int cnt = n / 256;
    float local[8];
    float ss = 0.f;
    for (int i = 0; i < cnt; i++) { float v = p[t + i * 256]; local[i] = v; ss += v * v; }
    float total = blockReduceSum(ss, sh);
    float scale = rsqrtf(total / (float)n + EPS_);
    for (int i = 0; i < cnt; i++) p[t + i * 256] = local[i] * scale * w[t + i * 256];
}

// ---------------- ckv split: rmsnorm first 512 -> g_ckvn ; rope last 64 -> g_kpe --------
__global__ __launch_bounds__(256) void ckv_split_kernel(const float* __restrict__ w) {
    __shared__ float sh[33];
    int s = blockIdx.x, t = threadIdx.x;
    const float* p = g_ckv + (size_t)s * CKVW_;
    float v0 = p[t], v1 = p[256 + t];
    float total = blockReduceSum(v0 * v0 + v1 * v1, sh);
    float scale = rsqrtf(total / (float)KVR_ + EPS_);
    g_ckvn[(size_t)s * KVR_ + t] = v0 * scale * w[t];
    g_ckvn[(size_t)s * KVR_ + 256 + t] = v1 * scale * w[256 + t];
    if (t < 32) {
        float x1 = p[KVR_ + t], x2 = p[KVR_ + 32 + t];
        float c = g_cosb[s * 32 + t], sn = g_sinb[s * 32 + t];
        g_kpe[s * ROPE_ + t] = x1 * c - x2 * sn;
        g_kpe[s * ROPE_ + 32 + t] = x2 * c + x1 * sn;
    }
}

// ---------------- layernorm + rope for ik (row length 128) ----------------
__global__ __launch_bounds__(128) void ik_ln_rope_kernel(const float* __restrict__ xin,
                                                         const float* __restrict__ w,
                                                         const float* __restrict__ b) {
    __shared__ float sh[33];
    __shared__ float sn_[128];
    int s = blockIdx.x, t = threadIdx.x;
    float x = xin[(size_t)s * ID_ + t];
    float mean = blockReduceSum(x, sh) / (float)ID_;
    float var = blockReduceSum(x * x, sh) / (float)ID_ - mean * mean;
    float nv = (x - mean) * rsqrtf(var + EPS_) * w[t] + b[t];
    sn_[t] = nv;
    __syncthreads();
    float out;
    if (t < 32) {
        float c = g_cosb[s * 32 + t], snv = g_sinb[s * 32 + t];
        out = sn_[t] * c - sn_[t + 32] * snv;
    } else if (t < 64) {
        float c = g_cosb[s * 32 + (t - 32)], snv = g_sinb[s * 32 + (t - 32)];
        out = sn_[t] * c + sn_[t - 32] * snv;
    } else {
        out = nv;
    }
    g_ik[(size_t)s * ID_ + t] = out;
}

// ---------------- generic in-place rope over heads ----------------
__global__ void rope_kernel(float* __restrict__ base, int rowStride, int headStride) {
    int s = blockIdx.x;
    int h = threadIdx.y, d = threadIdx.x;
    float* p = base + (size_t)s * rowStride + h * headStride;
    float c = g_cosb[s * 32 + d], sn = g_sinb[s * 32 + d];
    float x1 = p[d], x2 = p[d + 32];
    p[d] = x1 * c - x2 * sn;
    p[d + 32] = x2 * c + x1 * sn;
}

// ============ fused indexer w/ FFMA2 + causal skip ============
__global__ __launch_bounds__(256, 2) void idx_scores_kernel() {
    int m0 = blockIdx.y * 128, n0 = blockIdx.x * 64;
    int t = threadIdx.x;
    int tx = t & 15, ty = t >> 4;
    const float NINF = __int_as_float(0xff800000);

    if (m0 + 128 <= TOPK_) return;                 // rows never read by topk
    if (n0 >= m0 + 128) {                          // fully above diagonal
        #pragma unroll
        for (int i = 0; i < 8; i++) {
            int gm = m0 + ty * 8 + i;
            #pragma unroll
            for (int j = 0; j < 4; j++)
                g_scores[(size_t)gm * S_ + n0 + tx * 4 + j] = NINF;
        }
        return;
    }

    __shared__ float Bs[128][64];          // ik slab [k][n]
    __shared__ float As[2][8][128];        // iq chunk, double buffered
    int a_m = t >> 1, a_k = (t & 1) * 4;

    for (int i = t; i < 64 * 32; i += 256) {
        int nl = i >> 5, k4 = (i & 31) * 4;
        float4 v = *reinterpret_cast<const float4*>(&g_ik[(size_t)(n0 + nl) * ID_ + k4]);
        Bs[k4+0][nl] = v.x; Bs[k4+1][nl] = v.y; Bs[k4+2][nl] = v.z; Bs[k4+3][nl] = v.w;
    }

    float sacc[8][4];
    #pragma unroll
    for (int i = 0; i < 8; i++)
        #pragma unroll
        for (int j = 0; j < 4; j++) sacc[i][j] = 0.f;
    __syncthreads();

    const size_t lda = IH_ * ID_;
    for (int h = 0; h < IH_; h++) {
        const float* A = g_iq + (size_t)h * ID_ + (size_t)(m0 + a_m) * lda;
        {
            float4 v = *reinterpret_cast<const float4*>(&A[a_k]);
            As[0][a_k+0][a_m]=v.x; As[0][a_k+1][a_m]=v.y; As[0][a_k+2][a_m]=v.z; As[0][a_k+3][a_m]=v.w;
        }
        __syncthreads();
        u64 tacc[8][2];
        #pragma unroll
        for (int i = 0; i < 8; i++) { tacc[i][0] = 0ull; tacc[i][1] = 0ull; }
        int buf = 0;
        for (int k0 = 0; k0 < 128; k0 += 8) {
            float4 v;
            bool nxt = (k0 + 8) < 128;
            if (nxt) v = *reinterpret_cast<const float4*>(&A[k0 + 8 + a_k]);
            #pragma unroll
            for (int k = 0; k < 8; k++) {
                float4 a0 = *reinterpret_cast<const float4*>(&As[buf][k][ty * 8]);
                float4 a1 = *reinterpret_cast<const float4*>(&As[buf][k][ty * 8 + 4]);
                float4 b0 = *reinterpret_cast<const float4*>(&Bs[k0 + k][tx * 4]);
                u64 bb[2] = {pack2(b0.x,b0.y), pack2(b0.z,b0.w)};
                float ra[8] = {a0.x,a0.y,a0.z,a0.w,a1.x,a1.y,a1.z,a1.w};
                #pragma unroll
                for (int i = 0; i < 8; i++) {
                    u64 aa = pack2(ra[i], ra[i]);
                    ffma2(tacc[i][0], aa, bb[0]);
                    ffma2(tacc[i][1], aa, bb[1]);
                }
            }
            if (nxt) {
                int nb = buf ^ 1;
                As[nb][a_k+0][a_m]=v.x; As[nb][a_k+1][a_m]=v.y; As[nb][a_k+2][a_m]=v.z; As[nb][a_k+3][a_m]=v.w;
                __syncthreads();
                buf = nb;
            }
        }
        __syncthreads();   // protect As[0] for next head vs. last-chunk readers
        #pragma unroll
        for (int i = 0; i < 8; i++) {
            float w = g_iw[(size_t)(m0 + ty * 8 + i) * IH_ + h];   // warp-broadcast, L1-hot
            float2 t01 = unpack2(tacc[i][0]);
            float2 t23 = unpack2(tacc[i][1]);
            float tv[4] = {t01.x, t01.y, t23.x, t23.y};
            #pragma unroll
            for (int j = 0; j < 4; j++) {
                float add = __fmul_rn(w, fmaxf(tv[j], 0.f));   // separate roundings
                sacc[i][j] = __fadd_rn(sacc[i][j], add);       // (round-1 semantics)
            }
        }
    }
    #pragma unroll
    for (int i = 0; i < 8; i++) {
        int gm = m0 + ty * 8 + i;
        #pragma unroll
        for (int j = 0; j < 4; j++) {
            int gn = n0 + tx * 4 + j;
            g_scores[(size_t)gm * S_ + gn] = (gn <= gm) ? sacc[i][j] : NINF;
        }
    }
}

// ---------------- top-k (stable, jax tie semantics) ----------------
__device__ __forceinline__ unsigned fkey(float f) {
    unsigned u = __float_as_uint(f);
    return u ^ ((u >> 31) ? 0xFFFFFFFFu : 0x80000000u);
}

__global__ __launch_bounds__(256) void topk_kernel() {
    int q = blockIdx.x, t = threadIdx.x;
    const float* sc = g_scores + (size_t)q * S_;
    if (q < TOPK_) {
        for (int i = t; i <= q; i += 256) g_sel[(size_t)q * TOPK_ + i] = i;
        if (t == 0) g_nsel[q] = q + 1;
        return;
    }
    __shared__ unsigned hist[256];
    __shared__ unsigned s_pref, s_r;
    __shared__ int s_gt[257], s_eq[257];

    unsigned pref = 0, r = TOPK_;
    #pragma unroll
    for (int p = 3; p >= 0; p--) {
        hist[t] = 0;
        __syncthreads();
        for (int i = t; i < S_; i += 256) {
            unsigned u = fkey(sc[i]);
            bool ok = (p == 3) || ((u >> ((p + 1) * 8)) == pref);
            if (ok) atomicAdd(&hist[(u >> (p * 8)) & 255], 1u);
        }
        __syncthreads();
        if (t == 0) {
            unsigned run = 0;
            int b = 255;
            for (; b >= 0; b--) {
                unsigned c = hist[b];
                if (run + c >= r) break;
                run += c;
            }
            s_pref = (pref << 8) | (unsigned)b;
            s_r = r - run;
        }
        __syncthreads();
        pref = s_pref; r = s_r;
        __syncthreads();
    }
    unsigned T = pref;
    int need_eq = (int)r;

    int i0 = t * 8;
    unsigned keys[8];
    int cg = 0, ce = 0;
    #pragma unroll
    for (int k = 0; k < 8; k++) {
        unsigned u = fkey(sc[i0 + k]);
        keys[k] = u;
        cg += (u > T);
        ce += (u == T);
    }
    s_gt[t] = cg; s_eq[t] = ce;
    __syncthreads();
    if (t == 0) {
        int rg = 0, re = 0;
        for (int i = 0; i < 256; i++) {
            int a = s_gt[i]; s_gt[i] = rg; rg += a;
            int b2 = s_eq[i]; s_eq[i] = re; re += b2;
        }
        s_gt[256] = rg;
    }
    __syncthreads();
    int gpos = s_gt[t], epos = s_eq[t], total_gt = s_gt[256];
    int* out = g_sel + (size_t)q * TOPK_;
    #pragma unroll
    for (int k = 0; k < 8; k++) {
        unsigned u = keys[k];
        if (u > T) out[gpos++] = i0 + k;
        else if (u == T) {
            if (epos < need_eq) out[total_gt + epos] = i0 + k;
            epos++;
        }
    }
    if (t == 0) g_nsel[q] = TOPK_;
}

// ---------------- sparse attention over selected keys ----------------
__global__ __launch_bounds__(128) void sparse_attn_kernel() {
    const float SCALE = 0.07216878364870322f;
    int qi = blockIdx.x, h = blockIdx.y;
    int t = threadIdx.x, w = t >> 5, lane = t & 31;
    __shared__ float qv[192];
    __shared__ float s_p[TOPK_];
    __shared__ int s_idx[TOPK_];
    __shared__ float s_red[4];
    __shared__ float s_out[4][128];

    int n = g_nsel[qi];
    const float* qptr = g_q + (size_t)qi * (H_ * 192) + h * 192;
    for (int i = t; i < 192; i += 128) qv[i] = qptr[i];
    for (int i = t; i < n; i += 128) s_idx[i] = g_sel[(size_t)qi * TOPK_ + i];
    __syncthreads();

    for (int j = w; j < n; j += 4) {
        int kidx = s_idx[j];
        const float4* kn = reinterpret_cast<const float4*>(g_kv + (size_t)kidx * (H_ * 256) + h * 256);
        float4 a = reinterpret_cast<const float4*>(qv)[lane];
        float4 b = kn[lane];
        float d = a.x * b.x + a.y * b.y + a.z * b.z + a.w * b.w;
        const float2* kp = reinterpret_cast<const float2*>(g_kpe + (size_t)kidx * ROPE_);
        float2 ap = reinterpret_cast<const float2*>(qv + 128)[lane];
        float2 bp = kp[lane];
        d += ap.x * bp.x + ap.y * bp.y;
        #pragma unroll
        for (int o = 16; o; o >>= 1) d += __shfl_down_sync(0xffffffffu, d, o);
        if (lane == 0) s_p[j] = d * SCALE;
    }
    __syncthreads();

    float m = -3.4e38f;
    for (int i = t; i < n; i += 128) m = fmaxf(m, s_p[i]);
    #pragma unroll
    for (int o = 16; o; o >>= 1) m = fmaxf(m, __shfl_xor_sync(0xffffffffu, m, o));
    if (lane == 0) s_red[w] = m;
    __syncthreads();
    m = fmaxf(fmaxf(s_red[0], s_red[1]), fmaxf(s_red[2], s_red[3]));
    __syncthreads();

    float sum = 0.f;
    for (int i = t; i < n; i += 128) {
        float e = __expf(s_p[i] - m);
        s_p[i] = e;
        sum += e;
    }
    #pragma unroll
    for (int o = 16; o; o >>= 1) sum += __shfl_xor_sync(0xffffffffu, sum, o);
    __syncthreads();
    if (lane == 0) s_red[w] = sum;
    __syncthreads();
    sum = s_red[0] + s_red[1] + s_red[2] + s_red[3];
    float inv = 1.0f / sum;

    float4 acc = make_float4(0.f, 0.f, 0.f, 0.f);
    for (int j = w; j < n; j += 4) {
        float p = s_p[j];
        int kidx = s_idx[j];
        float4 v = reinterpret_cast<const float4*>(g_kv + (size_t)kidx * (H_ * 256) + h * 256 + 128)[lane];
        acc.x += p * v.x; acc.y += p * v.y; acc.z += p * v.z; acc.w += p * v.w;
    }
    reinterpret_cast<float4*>(&s_out[w][0])[lane] = acc;
    __syncthreads();
    float o = (s_out[0][t] + s_out[1][t] + s_out[2][t] + s_out[3][t]) * inv;
    g_attn[(size_t)qi * (H_ * VDIM_) + h * VDIM_ + t] = o;
}

// ---------------- launch ----------------
extern "C" void kernel_launch(void* const* d_in, const int* in_sizes, int n_in,
                              void* d_out, int out_size) {
    (void)in_sizes; (void)n_in; (void)out_size;
    const float* hidden      = (const float*)d_in[0];
    const float* q_a_w       = (const float*)d_in[1];
    const float* q_a_ln_w    = (const float*)d_in[2];
    const float* q_b_w       = (const float*)d_in[3];
    const float* kv_a_w      = (const float*)d_in[4];
    const float* kv_a_ln_w   = (const float*)d_in[5];
    const float* kv_b_w      = (const float*)d_in[6];
    const float* o_w         = (const float*)d_in[7];
    const float* idx_wq_b_w  = (const float*)d_in[8];
    const float* idx_wk_w    = (const float*)d_in[9];
    const float* idx_kn_w    = (const float*)d_in[10];
    const float* idx_kn_b    = (const float*)d_in[11];
    const float* idx_wproj_w = (const float*)d_in[12];
    float* out = (float*)d_out;

    float *p_qr, *p_q, *p_ckv, *p_ckvn, *p_kv, *p_iq, *p_ikpre, *p_iw, *p_attn;
    cudaGetSymbolAddress((void**)&p_qr,    g_qr);
    cudaGetSymbolAddress((void**)&p_q,     g_q);
    cudaGetSymbolAddress((void**)&p_ckv,   g_ckv);
    cudaGetSymbolAddress((void**)&p_ckvn,  g_ckvn);
    cudaGetSymbolAddress((void**)&p_kv,    g_kv);
    cudaGetSymbolAddress((void**)&p_iq,    g_iq);
    cudaGetSymbolAddress((void**)&p_ikpre, g_ikpre);
    cudaGetSymbolAddress((void**)&p_iw,    g_iw);
    cudaGetSymbolAddress((void**)&p_attn,  g_attn);

    dim3 tb(256);

    cossin_kernel<<<S_, 32>>>();

    // qr = rmsnorm(hidden @ q_a_w^T)
    sgemm_nt_db<<<dim3(QR_ / 128, S_ / 128), tb>>>(hidden, HID_, q_a_w, HID_, p_qr, QR_, S_, QR_, HID_, 1.f);
    rmsnorm_kernel<<<S_, 256>>>(p_qr, q_a_ln_w, QR_);

    // q = qr @ q_b_w^T   [S, 3072]
    sgemm_nt_db<<<dim3((H_ * 192) / 128, S_ / 128), tb>>>(p_qr, QR_, q_b_w, QR_, p_q, H_ * 192, S_, H_ * 192, QR_, 1.f);

    // ckv = hidden @ kv_a_w^T   [S, 576]
    sgemm_nt_db<<<dim3((CKVW_ + 127) / 128, S_ / 128), tb>>>(hidden, HID_, kv_a_w, HID_, p_ckv, CKVW_, S_, CKVW_, HID_, 1.f);
    ckv_split_kernel<<<S_, 256>>>(kv_a_ln_w);

    // kv = ckvn @ kv_b_w^T   [S, 4096]
    sgemm_nt_db<<<dim3((H_ * 256) / 128, S_ / 128), tb>>>(p_ckvn, KVR_, kv_b_w, KVR_, p_kv, H_ * 256, S_, H_ * 256, KVR_, 1.f);

    // iq = qr @ idx_wq_b_w^T   [S, 2048]
    sgemm_nt_db<<<dim3((IH_ * ID_) / 128, S_ / 128), tb>>>(p_qr, QR_, idx_wq_b_w, QR_, p_iq, IH_ * ID_, S_, IH_ * ID_, QR_, 1.f);

    // ik = ln+rope(hidden @ idx_wk_w^T)   [64x64 tiles, k-sequential]
    sgemm_nt_64<<<dim3(ID_ / 64, S_ / 64), tb>>>(hidden, HID_, idx_wk_w, HID_, p_ikpre, ID_, S_, ID_, HID_, 1.f);
    ik_ln_rope_kernel<<<S_, 128>>>(p_ikpre, idx_kn_w, idx_kn_b);

    // iw = hidden @ idx_wproj_w^T * 0.25   [64x64 tiles, N=16 bounds-guarded]
    sgemm_nt_64<<<dim3(1, S_ / 64), tb>>>(hidden, HID_, idx_wproj_w, HID_, p_iw, IH_, S_, IH_, HID_, 0.25f);

    // rope q_pe and iq
    rope_kernel<<<S_, dim3(32, H_)>>>(p_q + NOPE_, H_ * 192, 192);
    rope_kernel<<<S_, dim3(32, IH_)>>>(p_iq, IH_ * ID_, ID_);

    // fused indexer scores (causal skip + FFMA2)
    idx_scores_kernel<<<dim3(S_ / 64, S_ / 128), tb>>>();

    topk_kernel<<<S_, 256>>>();

    sparse_attn_kernel<<<dim3(S_, H_), 128>>>();

    // out = attn @ o_w^T   [S, 2048]
    sgemm_nt_db<<<dim3(HID_ / 128, S_ / 128), tb>>>(p_attn, H_ * VDIM_, o_w, H_ * VDIM_, out, HID_, S_, HID_, H_ * VDIM_, 1.f);
}

// round 8
// speedup vs baseline: 1.3372x; 1.0879x over previous
#include <cuda_runtime.h>
#include <math.h>

#define S_    2048
#define HID_  2048
#define H_    16
#define NOPE_ 128
#define ROPE_ 64
#define VDIM_ 128
#define QR_   1536
#define KVR_  512
#define IH_   16
#define ID_   128
#define TOPK_ 512
#define EPS_  1e-6f
#define CKVW_ (KVR_ + ROPE_)

typedef unsigned long long u64;

// ---------------- packed f32x2 helpers (bit-identical to two scalar FFMAs) ----------------
__device__ __forceinline__ void ffma2(u64 &d, u64 a, u64 b) {
    asm("fma.rn.f32x2 %0, %1, %2, %0;" : "+l"(d) : "l"(a), "l"(b));
}
__device__ __forceinline__ u64 pack2(float lo, float hi) {
    u64 r; asm("mov.b64 %0, {%1, %2};" : "=l"(r) : "f"(lo), "f"(hi)); return r;
}
__device__ __forceinline__ float2 unpack2(u64 v) {
    float2 r; asm("mov.b64 {%0, %1}, %2;" : "=f"(r.x), "=f"(r.y) : "l"(v)); return r;
}

// ---------------- scratch ----------------
__device__ float g_qr    [S_*QR_];
__device__ float g_q     [S_*H_*(NOPE_+ROPE_)];
__device__ float g_ckv   [S_*CKVW_];
__device__ float g_ckvn  [S_*KVR_];
__device__ float g_kpe   [S_*ROPE_];
__device__ float g_kv    [S_*H_*(NOPE_+VDIM_)];
__device__ float g_iq    [S_*IH_*ID_];
__device__ float g_ikpre [S_*ID_];
__device__ float g_ik    [S_*ID_];
__device__ float g_iw    [S_*IH_];
__device__ float g_scores[S_*S_];
__device__ int   g_sel   [S_*TOPK_];
__device__ int   g_nsel  [S_];
__device__ float g_attn  [S_*H_*VDIM_];
__device__ float g_cosb  [S_*32];
__device__ float g_sinb  [S_*32];

// ---------------- helpers ----------------
__device__ __forceinline__ float blockReduceSum(float v, float* sh) {
    int lane = threadIdx.x & 31, w = threadIdx.x >> 5;
    #pragma unroll
    for (int o = 16; o; o >>= 1) v += __shfl_xor_sync(0xffffffffu, v, o);
    if (lane == 0) sh[w] = v;
    __syncthreads();
    int nw = (blockDim.x + 31) >> 5;
    float r = (threadIdx.x < nw) ? sh[threadIdx.x] : 0.f;
    if (w == 0) {
        #pragma unroll
        for (int o = 16; o; o >>= 1) r += __shfl_xor_sync(0xffffffffu, r, o);
        if (lane == 0) sh[0] = r;
    }
    __syncthreads();
    float out = sh[0];
    __syncthreads();
    return out;
}

// ---------------- cos/sin (bit-exact numpy float32 path) ----------------
__global__ void cossin_kernel() {
    int s = blockIdx.x, d = threadIdx.x;
    float e = (float)(2 * d) / 64.0f;
    float pf = (float)pow(10000.0, (double)e);
    float inv = __fdiv_rn(1.0f, pf);
    float f = __fmul_rn((float)s, inv);
    g_cosb[s * 32 + d] = (float)cos((double)f);
    g_sinb[s * 32 + d] = (float)sin((double)f);
}

// ============ shared GEMM body: 128x128 tile, conflict-free quadrant microtile ============
// Per-output accumulation is strictly k-ascending with a single accumulator ->
// bit-identical results for any caller/tiling that uses this body.
__device__ __forceinline__ void gemm_body_128(
    const float* __restrict__ A, int lda,
    const float* __restrict__ B, int ldb,
    float* __restrict__ C, int ldc,
    int M, int N, int K, float alpha,
    int m0, int n0,
    float (*As)[8][128], float (*Bs)[8][128])
{
    int t = threadIdx.x;
    int tx = t & 15, ty = t >> 4;
    int a_m = t >> 1, a_k = (t & 1) * 4;
    int gmA = m0 + a_m, gnB = n0 + a_m;
    u64 acc[8][4];
    #pragma unroll
    for (int i = 0; i < 8; i++)
        #pragma unroll
        for (int j = 0; j < 4; j++) acc[i][j] = 0ull;

    float4 va = make_float4(0.f,0.f,0.f,0.f), vb = va;
    if (gmA < M) va = *reinterpret_cast<const float4*>(&A[(size_t)gmA * lda + a_k]);
    if (gnB < N) vb = *reinterpret_cast<const float4*>(&B[(size_t)gnB * ldb + a_k]);
    As[0][a_k+0][a_m]=va.x; As[0][a_k+1][a_m]=va.y; As[0][a_k+2][a_m]=va.z; As[0][a_k+3][a_m]=va.w;
    Bs[0][a_k+0][a_m]=vb.x; Bs[0][a_k+1][a_m]=vb.y; Bs[0][a_k+2][a_m]=vb.z; Bs[0][a_k+3][a_m]=vb.w;
    __syncthreads();
    int buf = 0;
    for (int k0 = 0; k0 < K; k0 += 8) {
        bool nxt = (k0 + 8) < K;
        if (nxt) {
            va = make_float4(0.f,0.f,0.f,0.f); vb = va;
            if (gmA < M) va = *reinterpret_cast<const float4*>(&A[(size_t)gmA * lda + k0 + 8 + a_k]);
            if (gnB < N) vb = *reinterpret_cast<const float4*>(&B[(size_t)gnB * ldb + k0 + 8 + a_k]);
        }
        #pragma unroll
        for (int k = 0; k < 8; k++) {
            float4 a0 = *reinterpret_cast<const float4*>(&As[buf][k][ty * 4]);
            float4 a1 = *reinterpret_cast<const float4*>(&As[buf][k][64 + ty * 4]);
            float4 b0 = *reinterpret_cast<const float4*>(&Bs[buf][k][tx * 4]);
            float4 b1 = *reinterpret_cast<const float4*>(&Bs[buf][k][64 + tx * 4]);
            u64 bb[4] = {pack2(b0.x,b0.y), pack2(b0.z,b0.w), pack2(b1.x,b1.y), pack2(b1.z,b1.w)};
            float ra[8] = {a0.x,a0.y,a0.z,a0.w,a1.x,a1.y,a1.z,a1.w};
            #pragma unroll
            for (int i = 0; i < 8; i++) {
                u64 aa = pack2(ra[i], ra[i]);
                #pragma unroll
                for (int j = 0; j < 4; j++) ffma2(acc[i][j], aa, bb[j]);
            }
        }
        if (nxt) {
            int nb = buf ^ 1;
            As[nb][a_k+0][a_m]=va.x; As[nb][a_k+1][a_m]=va.y; As[nb][a_k+2][a_m]=va.z; As[nb][a_k+3][a_m]=va.w;
            Bs[nb][a_k+0][a_m]=vb.x; Bs[nb][a_k+1][a_m]=vb.y; Bs[nb][a_k+2][a_m]=vb.z; Bs[nb][a_k+3][a_m]=vb.w;
            __syncthreads();
            buf = nb;
        }
    }
    #pragma unroll
    for (int i = 0; i < 8; i++) {
        int gm = m0 + ((i < 4) ? (ty * 4 + i) : (64 + ty * 4 + i - 4));
        if (gm >= M) continue;
        #pragma unroll
        for (int j = 0; j < 4; j++) {
            float2 v = unpack2(acc[i][j]);
            int gn = n0 + ((j < 2) ? (tx * 4 + j * 2) : (64 + tx * 4 + (j - 2) * 2));
            if (gn < N)     C[(size_t)gm * ldc + gn]     = alpha * v.x;
            if (gn + 1 < N) C[(size_t)gm * ldc + gn + 1] = alpha * v.y;
        }
    }
}

// ---------------- generic 128x128 GEMM (kv_b, o_w) ----------------
__global__ __launch_bounds__(256, 2) void sgemm_nt_db(
    const float* __restrict__ A, int lda,
    const float* __restrict__ B, int ldb,
    float* __restrict__ C, int ldc,
    int M, int N, int K, float alpha)
{
    __shared__ float As[2][8][128];
    __shared__ float Bs[2][8][128];
    gemm_body_128(A, lda, B, ldb, C, ldc, M, N, K, alpha,
                  blockIdx.y * 128, blockIdx.x * 128, As, Bs);
}

// ---------------- fused A=hidden (K=2048) GEMM: qr | ckv | ik | iw ----------------
// n-tile map: [0,12) qr(N=1536)  [12,17) ckv(N=576)  [17] ik(N=128)  [18] iw(N=16)
__global__ __launch_bounds__(256, 2) void fused_hidden_gemm(
    const float* __restrict__ A,
    const float* __restrict__ Bqr,  const float* __restrict__ Bckv,
    const float* __restrict__ Bik,  const float* __restrict__ Biw)
{
    __shared__ float As[2][8][128];
    __shared__ float Bs[2][8][128];
    int bx = blockIdx.x;
    const float* B; float* C; int N, ldc, n0; float alpha = 1.f;
    if (bx < 12)      { B = Bqr;  C = g_qr;    N = QR_;   ldc = QR_;   n0 = bx * 128; }
    else if (bx < 17) { B = Bckv; C = g_ckv;   N = CKVW_; ldc = CKVW_; n0 = (bx - 12) * 128; }
    else if (bx == 17){ B = Bik;  C = g_ikpre; N = ID_;   ldc = ID_;   n0 = 0; }
    else              { B = Biw;  C = g_iw;    N = IH_;   ldc = IH_;   n0 = 0; alpha = 0.25f; }
    gemm_body_128(A, HID_, B, HID_, C, ldc, S_, N, HID_, alpha,
                  blockIdx.y * 128, n0, As, Bs);
}

// ---------------- fused A=qr (K=1536) GEMM: q | iq ----------------
// n-tile map: [0,24) q(N=3072)  [24,40) iq(N=2048)
__global__ __launch_bounds__(256, 2) void fused_qr_gemm(
    const float* __restrict__ Bq, const float* __restrict__ Biq)
{
    __shared__ float As[2][8][128];
    __shared__ float Bs[2][8][128];
    int bx = blockIdx.x;
    const float* B; float* C; int N, n0;
    if (bx < 24) { B = Bq;  C = g_q;  N = H_ * 192;  n0 = bx * 128; }
    else         { B = Biq; C = g_iq; N = IH_ * ID_; n0 = (bx - 24) * 128; }
    gemm_body_128(g_qr, QR_, B, QR_, C, N, S_, N, QR_, 1.f,
                  blockIdx.y * 128, n0, As, Bs);
}

// ---------------- rmsnorm (in-place), row length n (n % 256 == 0) ----------------
__global__ __launch_bounds__(256) void rmsnorm_kernel(float* __restrict__ x,
                                                      const float* __restrict__ w, int n) {
    __shared__ float sh[33];
    int row = blockIdx.x, t = threadIdx.x;
    float* p = x + (size_t)row * n;
    int cnt = n / 256;
    float local[8];
    float ss = 0.f;
    for (int i = 0; i < cnt; i++) { float v = p[t + i * 256]; local[i] = v; ss += v * v; }
    float total = blockReduceSum(ss, sh);
    float scale = rsqrtf(total / (float)n + EPS_);
    for (int i = 0; i < cnt; i++) p[t + i * 256] = local[i] * scale * w[t + i * 256];
}

// ---------------- ckv split: rmsnorm first 512 -> g_ckvn ; rope last 64 -> g_kpe --------
__global__ __launch_bounds__(256) void ckv_split_kernel(const float* __restrict__ w) {
    __shared__ float sh[33];
    int s = blockIdx.x, t = threadIdx.x;
    const float* p = g_ckv + (size_t)s * CKVW_;
    float v0 = p[t], v1 = p[256 + t];
    float total = blockReduceSum(v0 * v0 + v1 * v1, sh);
    float scale = rsqrtf(total / (float)KVR_ + EPS_);
    g_ckvn[(size_t)s * KVR_ + t] = v0 * scale * w[t];
    g_ckvn[(size_t)s * KVR_ + 256 + t] = v1 * scale * w[256 + t];
    if (t < 32) {
        float x1 = p[KVR_ + t], x2 = p[KVR_ + 32 + t];
        float c = g_cosb[s * 32 + t], sn = g_sinb[s * 32 + t];
        g_kpe[s * ROPE_ + t] = x1 * c - x2 * sn;
        g_kpe[s * ROPE_ + 32 + t] = x2 * c + x1 * sn;
    }
}

// ---------------- layernorm + rope for ik (row length 128) ----------------
__global__ __launch_bounds__(128) void ik_ln_rope_kernel(const float* __restrict__ xin,
                                                         const float* __restrict__ w,
                                                         const float* __restrict__ b) {
    __shared__ float sh[33];
    __shared__ float sn_[128];
    int s = blockIdx.x, t = threadIdx.x;
    float x = xin[(size_t)s * ID_ + t];
    float mean = blockReduceSum(x, sh) / (float)ID_;
    float var = blockReduceSum(x * x, sh) / (float)ID_ - mean * mean;
    float nv = (x - mean) * rsqrtf(var + EPS_) * w[t] + b[t];
    sn_[t] = nv;
    __syncthreads();
    float out;
    if (t < 32) {
        float c = g_cosb[s * 32 + t], snv = g_sinb[s * 32 + t];
        out = sn_[t] * c - sn_[t + 32] * snv;
    } else if (t < 64) {
        float c = g_cosb[s * 32 + (t - 32)], snv = g_sinb[s * 32 + (t - 32)];
        out = sn_[t] * c + sn_[t - 32] * snv;
    } else {
        out = nv;
    }
    g_ik[(size_t)s * ID_ + t] = out;
}

// ---------------- generic in-place rope over heads ----------------
__global__ void rope_kernel(float* __restrict__ base, int rowStride, int headStride) {
    int s = blockIdx.x;
    int h = threadIdx.y, d = threadIdx.x;
    float* p = base + (size_t)s * rowStride + h * headStride;
    float c = g_cosb[s * 32 + d], sn = g_sinb[s * 32 + d];
    float x1 = p[d], x2 = p[d + 32];
    p[d] = x1 * c - x2 * sn;
    p[d + 32] = x2 * c + x1 * sn;
}

// ============ fused indexer w/ FFMA2 + causal skip ============
__global__ __launch_bounds__(256, 2) void idx_scores_kernel() {
    int m0 = blockIdx.y * 128, n0 = blockIdx.x * 64;
    int t = threadIdx.x;
    int tx = t & 15, ty = t >> 4;
    const float NINF = __int_as_float(0xff800000);

    if (m0 + 128 <= TOPK_) return;                 // rows never read by topk
    if (n0 >= m0 + 128) {                          // fully above diagonal
        #pragma unroll
        for (int i = 0; i < 8; i++) {
            int gm = m0 + ty * 8 + i;
            #pragma unroll
            for (int j = 0; j < 4; j++)
                g_scores[(size_t)gm * S_ + n0 + tx * 4 + j] = NINF;
        }
        return;
    }

    __shared__ float Bs[128][64];          // ik slab [k][n]
    __shared__ float As[2][8][128];        // iq chunk, double buffered
    int a_m = t >> 1, a_k = (t & 1) * 4;

    for (int i = t; i < 64 * 32; i += 256) {
        int nl = i >> 5, k4 = (i & 31) * 4;
        float4 v = *reinterpret_cast<const float4*>(&g_ik[(size_t)(n0 + nl) * ID_ + k4]);
        Bs[k4+0][nl] = v.x; Bs[k4+1][nl] = v.y; Bs[k4+2][nl] = v.z; Bs[k4+3][nl] = v.w;
    }

    float sacc[8][4];
    #pragma unroll
    for (int i = 0; i < 8; i++)
        #pragma unroll
        for (int j = 0; j < 4; j++) sacc[i][j] = 0.f;
    __syncthreads();

    const size_t lda = IH_ * ID_;
    for (int h = 0; h < IH_; h++) {
        const float* A = g_iq + (size_t)h * ID_ + (size_t)(m0 + a_m) * lda;
        {
            float4 v = *reinterpret_cast<const float4*>(&A[a_k]);
            As[0][a_k+0][a_m]=v.x; As[0][a_k+1][a_m]=v.y; As[0][a_k+2][a_m]=v.z; As[0][a_k+3][a_m]=v.w;
        }
        __syncthreads();
        u64 tacc[8][2];
        #pragma unroll
        for (int i = 0; i < 8; i++) { tacc[i][0] = 0ull; tacc[i][1] = 0ull; }
        int buf = 0;
        for (int k0 = 0; k0 < 128; k0 += 8) {
            float4 v;
            bool nxt = (k0 + 8) < 128;
            if (nxt) v = *reinterpret_cast<const float4*>(&A[k0 + 8 + a_k]);
            #pragma unroll
            for (int k = 0; k < 8; k++) {
                float4 a0 = *reinterpret_cast<const float4*>(&As[buf][k][ty * 8]);
                float4 a1 = *reinterpret_cast<const float4*>(&As[buf][k][ty * 8 + 4]);
                float4 b0 = *reinterpret_cast<const float4*>(&Bs[k0 + k][tx * 4]);
                u64 bb[2] = {pack2(b0.x,b0.y), pack2(b0.z,b0.w)};
                float ra[8] = {a0.x,a0.y,a0.z,a0.w,a1.x,a1.y,a1.z,a1.w};
                #pragma unroll
                for (int i = 0; i < 8; i++) {
                    u64 aa = pack2(ra[i], ra[i]);
                    ffma2(tacc[i][0], aa, bb[0]);
                    ffma2(tacc[i][1], aa, bb[1]);
                }
            }
            if (nxt) {
                int nb = buf ^ 1;
                As[nb][a_k+0][a_m]=v.x; As[nb][a_k+1][a_m]=v.y; As[nb][a_k+2][a_m]=v.z; As[nb][a_k+3][a_m]=v.w;
                __syncthreads();
                buf = nb;
            }
        }
        __syncthreads();   // protect As[0] for next head vs. last-chunk readers
        #pragma unroll
        for (int i = 0; i < 8; i++) {
            float w = g_iw[(size_t)(m0 + ty * 8 + i) * IH_ + h];   // warp-broadcast, L1-hot
            float2 t01 = unpack2(tacc[i][0]);
            float2 t23 = unpack2(tacc[i][1]);
            float tv[4] = {t01.x, t01.y, t23.x, t23.y};
            #pragma unroll
            for (int j = 0; j < 4; j++) {
                float add = __fmul_rn(w, fmaxf(tv[j], 0.f));   // separate roundings
                sacc[i][j] = __fadd_rn(sacc[i][j], add);       // (round-1 semantics)
            }
        }
    }
    #pragma unroll
    for (int i = 0; i < 8; i++) {
        int gm = m0 + ty * 8 + i;
        #pragma unroll
        for (int j = 0; j < 4; j++) {
            int gn = n0 + tx * 4 + j;
            g_scores[(size_t)gm * S_ + gn] = (gn <= gm) ? sacc[i][j] : NINF;
        }
    }
}

// ---------------- top-k (stable, jax tie semantics) ----------------
__device__ __forceinline__ unsigned fkey(float f) {
    unsigned u = __float_as_uint(f);
    return u ^ ((u >> 31) ? 0xFFFFFFFFu : 0x80000000u);
}

__global__ __launch_bounds__(256) void topk_kernel() {
    int q = blockIdx.x, t = threadIdx.x;
    const float* sc = g_scores + (size_t)q * S_;
    if (q < TOPK_) {
        for (int i = t; i <= q; i += 256) g_sel[(size_t)q * TOPK_ + i] = i;
        if (t == 0) g_nsel[q] = q + 1;
        return;
    }
    __shared__ unsigned hist[256];
    __shared__ unsigned s_pref, s_r;
    __shared__ int s_gt[257], s_eq[257];

    unsigned pref = 0, r = TOPK_;
    #pragma unroll
    for (int p = 3; p >= 0; p--) {
        hist[t] = 0;
        __syncthreads();
        for (int i = t; i < S_; i += 256) {
            unsigned u = fkey(sc[i]);
            bool ok = (p == 3) || ((u >> ((p + 1) * 8)) == pref);
            if (ok) atomicAdd(&hist[(u >> (p * 8)) & 255], 1u);
        }
        __syncthreads();
        if (t == 0) {
            unsigned run = 0;
            int b = 255;
            for (; b >= 0; b--) {
                unsigned c = hist[b];
                if (run + c >= r) break;
                run += c;
            }
            s_pref = (pref << 8) | (unsigned)b;
            s_r = r - run;
        }
        __syncthreads();
        pref = s_pref; r = s_r;
        __syncthreads();
    }
    unsigned T = pref;
    int need_eq = (int)r;

    int i0 = t * 8;
    unsigned keys[8];
    int cg = 0, ce = 0;
    #pragma unroll
    for (int k = 0; k < 8; k++) {
        unsigned u = fkey(sc[i0 + k]);
        keys[k] = u;
        cg += (u > T);
        ce += (u == T);
    }
    s_gt[t] = cg; s_eq[t] = ce;
    __syncthreads();
    if (t == 0) {
        int rg = 0, re = 0;
        for (int i = 0; i < 256; i++) {
            int a = s_gt[i]; s_gt[i] = rg; rg += a;
            int b2 = s_eq[i]; s_eq[i] = re; re += b2;
        }
        s_gt[256] = rg;
    }
    __syncthreads();
    int gpos = s_gt[t], epos = s_eq[t], total_gt = s_gt[256];
    int* out = g_sel + (size_t)q * TOPK_;
    #pragma unroll
    for (int k = 0; k < 8; k++) {
        unsigned u = keys[k];
        if (u > T) out[gpos++] = i0 + k;
        else if (u == T) {
            if (epos < need_eq) out[total_gt + epos] = i0 + k;
            epos++;
        }
    }
    if (t == 0) g_nsel[q] = TOPK_;
}

// ---------------- sparse attention over selected keys ----------------
__global__ __launch_bounds__(128) void sparse_attn_kernel() {
    const float SCALE = 0.07216878364870322f;
    int qi = blockIdx.x, h = blockIdx.y;
    int t = threadIdx.x, w = t >> 5, lane = t & 31;
    __shared__ float qv[192];
    __shared__ float s_p[TOPK_];
    __shared__ int s_idx[TOPK_];
    __shared__ float s_red[4];
    __shared__ float s_out[4][128];

    int n = g_nsel[qi];
    const float* qptr = g_q + (size_t)qi * (H_ * 192) + h * 192;
    for (int i = t; i < 192; i += 128) qv[i] = qptr[i];
    for (int i = t; i < n; i += 128) s_idx[i] = g_sel[(size_t)qi * TOPK_ + i];
    __syncthreads();

    for (int j = w; j < n; j += 4) {
        int kidx = s_idx[j];
        const float4* kn = reinterpret_cast<const float4*>(g_kv + (size_t)kidx * (H_ * 256) + h * 256);
        float4 a = reinterpret_cast<const float4*>(qv)[lane];
        float4 b = kn[lane];
        float d = a.x * b.x + a.y * b.y + a.z * b.z + a.w * b.w;
        const float2* kp = reinterpret_cast<const float2*>(g_kpe + (size_t)kidx * ROPE_);
        float2 ap = reinterpret_cast<const float2*>(qv + 128)[lane];
        float2 bp = kp[lane];
        d += ap.x * bp.x + ap.y * bp.y;
        #pragma unroll
        for (int o = 16; o; o >>= 1) d += __shfl_down_sync(0xffffffffu, d, o);
        if (lane == 0) s_p[j] = d * SCALE;
    }
    __syncthreads();

    float m = -3.4e38f;
    for (int i = t; i < n; i += 128) m = fmaxf(m, s_p[i]);
    #pragma unroll
    for (int o = 16; o; o >>= 1) m = fmaxf(m, __shfl_xor_sync(0xffffffffu, m, o));
    if (lane == 0) s_red[w] = m;
    __syncthreads();
    m = fmaxf(fmaxf(s_red[0], s_red[1]), fmaxf(s_red[2], s_red[3]));
    __syncthreads();

    float sum = 0.f;
    for (int i = t; i < n; i += 128) {
        float e = __expf(s_p[i] - m);
        s_p[i] = e;
        sum += e;
    }
    #pragma unroll
    for (int o = 16; o; o >>= 1) sum += __shfl_xor_sync(0xffffffffu, sum, o);
    __syncthreads();
    if (lane == 0) s_red[w] = sum;
    __syncthreads();
    sum = s_red[0] + s_red[1] + s_red[2] + s_red[3];
    float inv = 1.0f / sum;

    float4 acc = make_float4(0.f, 0.f, 0.f, 0.f);
    for (int j = w; j < n; j += 4) {
        float p = s_p[j];
        int kidx = s_idx[j];
        float4 v = reinterpret_cast<const float4*>(g_kv + (size_t)kidx * (H_ * 256) + h * 256 + 128)[lane];
        acc.x += p * v.x; acc.y += p * v.y; acc.z += p * v.z; acc.w += p * v.w;
    }
    reinterpret_cast<float4*>(&s_out[w][0])[lane] = acc;
    __syncthreads();
    float o = (s_out[0][t] + s_out[1][t] + s_out[2][t] + s_out[3][t]) * inv;
    g_attn[(size_t)qi * (H_ * VDIM_) + h * VDIM_ + t] = o;
}

// ---------------- launch ----------------
extern "C" void kernel_launch(void* const* d_in, const int* in_sizes, int n_in,
                              void* d_out, int out_size) {
    (void)in_sizes; (void)n_in; (void)out_size;
    const float* hidden      = (const float*)d_in[0];
    const float* q_a_w       = (const float*)d_in[1];
    const float* q_a_ln_w    = (const float*)d_in[2];
    const float* q_b_w       = (const float*)d_in[3];
    const float* kv_a_w      = (const float*)d_in[4];
    const float* kv_a_ln_w   = (const float*)d_in[5];
    const float* kv_b_w      = (const float*)d_in[6];
    const float* o_w         = (const float*)d_in[7];
    const float* idx_wq_b_w  = (const float*)d_in[8];
    const float* idx_wk_w    = (const float*)d_in[9];
    const float* idx_kn_w    = (const float*)d_in[10];
    const float* idx_kn_b    = (const float*)d_in[11];
    const float* idx_wproj_w = (const float*)d_in[12];
    float* out = (float*)d_out;

    float *p_qr, *p_q, *p_ckvn, *p_kv, *p_iq, *p_ikpre, *p_attn;
    cudaGetSymbolAddress((void**)&p_qr,    g_qr);
    cudaGetSymbolAddress((void**)&p_q,     g_q);
    cudaGetSymbolAddress((void**)&p_ckvn,  g_ckvn);
    cudaGetSymbolAddress((void**)&p_kv,    g_kv);
    cudaGetSymbolAddress((void**)&p_iq,    g_iq);
    cudaGetSymbolAddress((void**)&p_ikpre, g_ikpre);
    cudaGetSymbolAddress((void**)&p_attn,  g_attn);

    dim3 tb(256);

    cossin_kernel<<<S_, 32>>>();

    // qr | ckv | ik | iw — one fused wave over A=hidden (K=2048)
    fused_hidden_gemm<<<dim3(19, S_ / 128), tb>>>(hidden, q_a_w, kv_a_w, idx_wk_w, idx_wproj_w);
    rmsnorm_kernel<<<S_, 256>>>(p_qr, q_a_ln_w, QR_);
    ckv_split_kernel<<<S_, 256>>>(kv_a_ln_w);
    ik_ln_rope_kernel<<<S_, 128>>>(p_ikpre, idx_kn_w, idx_kn_b);

    // q | iq — one fused launch over A=qr (K=1536)
    fused_qr_gemm<<<dim3(40, S_ / 128), tb>>>(q_b_w, idx_wq_b_w);

    // kv = ckvn @ kv_b_w^T   [S, 4096]
    sgemm_nt_db<<<dim3((H_ * 256) / 128, S_ / 128), tb>>>(p_ckvn, KVR_, kv_b_w, KVR_, p_kv, H_ * 256, S_, H_ * 256, KVR_, 1.f);

    // rope q_pe and iq
    rope_kernel<<<S_, dim3(32, H_)>>>(p_q + NOPE_, H_ * 192, 192);
    rope_kernel<<<S_, dim3(32, IH_)>>>(p_iq, IH_ * ID_, ID_);

    // fused indexer scores (causal skip + FFMA2)
    idx_scores_kernel<<<dim3(S_ / 64, S_ / 128), tb>>>();

    topk_kernel<<<S_, 256>>>();

    sparse_attn_kernel<<<dim3(S_, H_), 128>>>();

    // out = attn @ o_w^T   [S, 2048]
    sgemm_nt_db<<<dim3(HID_ / 128, S_ / 128), tb>>>(p_attn, H_ * VDIM_, o_w, H_ * VDIM_, out, HID_, S_, HID_, H_ * VDIM_, 1.f);
}